// round 2
// baseline (speedup 1.0000x reference)
#include <cuda_runtime.h>
#include <cuda_bf16.h>

#define NN 20000
#define NE 320000
#define NG 256
#define DIM 256
#define NLAYER 4
#define EPS_BN 1e-5f
#define NB_STAT 157   // ceil(20000/128)

// ---------------- device scratch (static, no allocation) ----------------
__device__ __align__(16) float g_x[(size_t)NN * DIM];
__device__ __align__(16) float g_agg[(size_t)NN * DIM];
__device__ __align__(16) float g_h[(size_t)NN * DIM];
__device__ float g_invdeg[NN];
__device__ int   g_deg[NN];
__device__ int   g_fillpos[NN];
__device__ int   g_rowptr[NN + 1];
__device__ int   g_colidx[NE];
__device__ float g_psum[NB_STAT * DIM];
__device__ float g_psum2[NB_STAT * DIM];
__device__ float g_bn_a[DIM];
__device__ float g_bn_b[DIM];
__device__ int   g_gstart[NG + 1];
__device__ float g_pool[NG * DIM];
__device__ float g_mlp1[NG * 128];
__device__ float g_mlp2[NG * 64];

// ---------------- graph structure build ----------------
__global__ void zero_int_kernel() {
    int i = blockIdx.x * blockDim.x + threadIdx.x;
    if (i < NN) { g_deg[i] = 0; g_fillpos[i] = 0; }
}

__global__ void deg_kernel(const int* __restrict__ ei) {
    int e = blockIdx.x * blockDim.x + threadIdx.x;
    if (e >= NE) return;
    int dst = ei[NE + e];
    atomicAdd(&g_deg[dst], 1);
}

__global__ void invdeg_kernel() {
    int i = blockIdx.x * blockDim.x + threadIdx.x;
    if (i >= NN) return;
    int d = g_deg[i];
    g_invdeg[i] = (d > 0) ? 1.0f / (float)d : 0.0f;
}

// single-block exclusive scan of g_deg -> g_rowptr
__global__ void scan_kernel() {
    __shared__ int sh[1024];
    int tid = threadIdx.x;
    int offset = 0;
    for (int base = 0; base < NN; base += 1024) {
        int i = base + tid;
        int v = (i < NN) ? g_deg[i] : 0;
        sh[tid] = v;
        __syncthreads();
        for (int s = 1; s < 1024; s <<= 1) {
            int t = (tid >= s) ? sh[tid - s] : 0;
            __syncthreads();
            sh[tid] += t;
            __syncthreads();
        }
        if (i < NN) g_rowptr[i] = offset + sh[tid] - v;
        int total = sh[1023];
        __syncthreads();
        offset += total;
    }
    if (tid == 0) g_rowptr[NN] = offset;
}

__global__ void fill_kernel(const int* __restrict__ ei) {
    int e = blockIdx.x * blockDim.x + threadIdx.x;
    if (e >= NE) return;
    int src = ei[e];
    int dst = ei[NE + e];
    int p = atomicAdd(&g_fillpos[dst], 1);
    g_colidx[g_rowptr[dst] + p] = src;
}

// sort each adjacency list (determinism of fp32 sum order)
__global__ void sort_adj_kernel() {
    int v = blockIdx.x * blockDim.x + threadIdx.x;
    if (v >= NN) return;
    int b = g_rowptr[v], e = g_rowptr[v + 1];
    for (int i = b + 1; i < e; i++) {
        int key = g_colidx[i];
        int j = i - 1;
        while (j >= b && g_colidx[j] > key) { g_colidx[j + 1] = g_colidx[j]; j--; }
        g_colidx[j + 1] = key;
    }
}

// ---------------- feature copy ----------------
__global__ void copy_x_kernel(const float* __restrict__ x) {
    size_t i = (size_t)(blockIdx.x * blockDim.x + threadIdx.x) * 4;
    size_t total = (size_t)NN * DIM;
    if (i < total) {
        float4 v = *(const float4*)(x + i);
        *(float4*)(g_x + i) = v;
    }
}

// ---------------- mean aggregation: warp per node ----------------
__global__ void gather_kernel() {
    int warp = (blockIdx.x * blockDim.x + threadIdx.x) >> 5;
    int lane = threadIdx.x & 31;
    if (warp >= NN) return;
    int b = g_rowptr[warp], e = g_rowptr[warp + 1];
    int col = lane * 8;
    float acc0 = 0, acc1 = 0, acc2 = 0, acc3 = 0, acc4 = 0, acc5 = 0, acc6 = 0, acc7 = 0;
    for (int j = b; j < e; j++) {
        int u = g_colidx[j];
        const float4* p = (const float4*)(g_x + (size_t)u * DIM + col);
        float4 a = p[0];
        float4 c = p[1];
        acc0 += a.x; acc1 += a.y; acc2 += a.z; acc3 += a.w;
        acc4 += c.x; acc5 += c.y; acc6 += c.z; acc7 += c.w;
    }
    float s = g_invdeg[warp];
    float4 o0 = make_float4(acc0 * s, acc1 * s, acc2 * s, acc3 * s);
    float4 o1 = make_float4(acc4 * s, acc5 * s, acc6 * s, acc7 * s);
    float4* q = (float4*)(g_agg + (size_t)warp * DIM + col);
    q[0] = o0;
    q[1] = o1;
}

// ---------------- GEMM: h = agg @ Wl + x @ Wr + bl ----------------
#define BM 64
#define BN 64
#define BK 16
__global__ void gemm_kernel(const float* __restrict__ Wl, const float* __restrict__ Wr,
                            const float* __restrict__ bl) {
    __shared__ float As[BK][BM + 4];
    __shared__ float Ws[BK][BN];
    int tid = threadIdx.x;
    int n0 = blockIdx.x * BN;
    int m0 = blockIdx.y * BM;
    int ty = tid >> 4, tx = tid & 15;
    float acc[4][4];
#pragma unroll
    for (int i = 0; i < 4; i++)
#pragma unroll
        for (int j = 0; j < 4; j++) acc[i][j] = 0.0f;

    int ka = tid & 15;
    int ma = tid >> 4;
    for (int kk = 0; kk < 2 * DIM; kk += BK) {
        const float* Asrc = (kk < DIM) ? g_agg : g_x;
        const float* Wsrc = (kk < DIM) ? Wl : Wr;
        int kglob = (kk < DIM) ? kk : kk - DIM;
#pragma unroll
        for (int r = 0; r < 4; r++) {
            int m = m0 + ma + r * 16;
            float v = 0.0f;
            if (m < NN) v = Asrc[(size_t)m * DIM + kglob + ka];
            As[ka][ma + r * 16] = v;
        }
#pragma unroll
        for (int r = 0; r < 4; r++) {
            int k = (tid >> 6) + r * 4;
            int n = tid & 63;
            Ws[k][n] = Wsrc[(size_t)(kglob + k) * DIM + n0 + n];
        }
        __syncthreads();
#pragma unroll
        for (int k = 0; k < BK; k++) {
            float4 a = *(const float4*)&As[k][ty * 4];
            float4 w = *(const float4*)&Ws[k][tx * 4];
            float av[4] = {a.x, a.y, a.z, a.w};
            float wv[4] = {w.x, w.y, w.z, w.w};
#pragma unroll
            for (int i = 0; i < 4; i++)
#pragma unroll
                for (int j = 0; j < 4; j++) acc[i][j] += av[i] * wv[j];
        }
        __syncthreads();
    }
    float4 bv = *(const float4*)(bl + n0 + tx * 4);
    float bvv[4] = {bv.x, bv.y, bv.z, bv.w};
#pragma unroll
    for (int i = 0; i < 4; i++) {
        int m = m0 + ty * 4 + i;
        if (m >= NN) continue;
        float4 o;
        o.x = acc[i][0] + bvv[0];
        o.y = acc[i][1] + bvv[1];
        o.z = acc[i][2] + bvv[2];
        o.w = acc[i][3] + bvv[3];
        *(float4*)(g_h + (size_t)m * DIM + n0 + tx * 4) = o;
    }
}

// ---------------- BatchNorm ----------------
__global__ void bn_stat_kernel() {
    int b = blockIdx.x;
    int d = threadIdx.x;
    int r0 = b * 128;
    int r1 = r0 + 128;
    if (r1 > NN) r1 = NN;
    float s = 0, s2 = 0;
    for (int r = r0; r < r1; r++) {
        float v = g_h[(size_t)r * DIM + d];
        s += v;
        s2 += v * v;
    }
    g_psum[b * DIM + d] = s;
    g_psum2[b * DIM + d] = s2;
}

__global__ void bn_reduce_kernel(const float* __restrict__ gamma, const float* __restrict__ beta) {
    int d = threadIdx.x;
    float s = 0, s2 = 0;
    for (int b = 0; b < NB_STAT; b++) {
        s += g_psum[b * DIM + d];
        s2 += g_psum2[b * DIM + d];
    }
    float mu = s / (float)NN;
    float var = s2 / (float)NN - mu * mu;
    float r = rsqrtf(var + EPS_BN);
    float a = gamma[d] * r;
    g_bn_a[d] = a;
    g_bn_b[d] = beta[d] - mu * a;
}

__global__ void bn_apply_kernel() {
    int row = blockIdx.x;
    int d = threadIdx.x;
    size_t idx = (size_t)row * DIM + d;
    float v = g_h[idx];
    g_x[idx] = fmaxf(v * g_bn_a[d] + g_bn_b[d], 0.0f);
}

// ---------------- pooling ----------------
__global__ void pool_bounds_kernel(const int* __restrict__ batch) {
    int g = threadIdx.x;
    if (g < NG) {
        int lo = 0, hi = NN;
        while (lo < hi) {
            int mid = (lo + hi) >> 1;
            if (batch[mid] < g) lo = mid + 1; else hi = mid;
        }
        g_gstart[g] = lo;
    }
    if (g == 0) g_gstart[NG] = NN;
}

__global__ void pool_kernel() {
    int g = blockIdx.x;
    int d = threadIdx.x;
    int r0 = g_gstart[g], r1 = g_gstart[g + 1];
    float s = 0;
    for (int r = r0; r < r1; r++) s += g_x[(size_t)r * DIM + d];
    int c = r1 - r0;
    g_pool[g * DIM + d] = s / (float)(c > 0 ? c : 1);
}

// ---------------- MLP ----------------
__global__ void mlp1_kernel(const float* __restrict__ w, const float* __restrict__ bias) {
    __shared__ float xr[256];
    int g = blockIdx.x, n = threadIdx.x;
    xr[n] = g_pool[g * 256 + n];
    xr[n + 128] = g_pool[g * 256 + n + 128];
    __syncthreads();
    float s = bias[n];
#pragma unroll 8
    for (int k = 0; k < 256; k++) s += xr[k] * w[k * 128 + n];
    g_mlp1[g * 128 + n] = fmaxf(s, 0.0f);
}

__global__ void mlp2_kernel(const float* __restrict__ w, const float* __restrict__ bias) {
    __shared__ float xr[128];
    int g = blockIdx.x, n = threadIdx.x;
    xr[n] = g_mlp1[g * 128 + n];
    xr[n + 64] = g_mlp1[g * 128 + n + 64];
    __syncthreads();
    float s = bias[n];
#pragma unroll 8
    for (int k = 0; k < 128; k++) s += xr[k] * w[k * 64 + n];
    g_mlp2[g * 64 + n] = fmaxf(s, 0.0f);
}

__global__ void mlp3_kernel(const float* __restrict__ w, const float* __restrict__ bias,
                            float* __restrict__ out) {
    __shared__ float xr[64];
    int g = blockIdx.x, n = threadIdx.x;
    if (n < 32) { xr[n] = g_mlp2[g * 64 + n]; xr[n + 32] = g_mlp2[g * 64 + n + 32]; }
    __syncthreads();
    if (n >= 10) return;
    float s = bias[n];
#pragma unroll 8
    for (int k = 0; k < 64; k++) s += xr[k] * w[k * 10 + n];
    out[g * 10 + n] = s;
}

// ---------------- host launch ----------------
extern "C" void kernel_launch(void* const* d_in, const int* in_sizes, int n_in,
                              void* d_out, int out_size) {
    const float* x     = (const float*)d_in[0];
    const int*   ei    = (const int*)d_in[1];     // int32 on the wire (JAX x64 disabled)
    const int*   batch = (const int*)d_in[2];
    const float* Wl    = (const float*)d_in[3];
    const float* bl    = (const float*)d_in[4];
    const float* Wr    = (const float*)d_in[5];
    const float* gamma = (const float*)d_in[6];
    const float* beta  = (const float*)d_in[7];
    const float* fc1_w = (const float*)d_in[8];
    const float* fc1_b = (const float*)d_in[9];
    const float* fc2_w = (const float*)d_in[10];
    const float* fc2_b = (const float*)d_in[11];
    const float* fc3_w = (const float*)d_in[12];
    const float* fc3_b = (const float*)d_in[13];
    float* out = (float*)d_out;

    // graph structure (recomputed each call; same inputs -> same result)
    zero_int_kernel<<<(NN + 255) / 256, 256>>>();
    deg_kernel<<<(NE + 255) / 256, 256>>>(ei);
    invdeg_kernel<<<(NN + 255) / 256, 256>>>();
    scan_kernel<<<1, 1024>>>();
    fill_kernel<<<(NE + 255) / 256, 256>>>(ei);
    sort_adj_kernel<<<(NN + 255) / 256, 256>>>();

    copy_x_kernel<<<(NN * DIM / 4 + 255) / 256, 256>>>(x);

    dim3 gemm_grid(DIM / BN, (NN + BM - 1) / BM);
    for (int i = 0; i < NLAYER; i++) {
        gather_kernel<<<(NN * 32 + 255) / 256, 256>>>();
        gemm_kernel<<<gemm_grid, 256>>>(Wl + (size_t)i * DIM * DIM,
                                        Wr + (size_t)i * DIM * DIM,
                                        bl + (size_t)i * DIM);
        bn_stat_kernel<<<NB_STAT, DIM>>>();
        bn_reduce_kernel<<<1, DIM>>>(gamma + (size_t)i * DIM, beta + (size_t)i * DIM);
        bn_apply_kernel<<<NN, DIM>>>();
    }

    pool_bounds_kernel<<<1, 256>>>(batch);
    pool_kernel<<<NG, DIM>>>();
    mlp1_kernel<<<NG, 128>>>(fc1_w, fc1_b);
    mlp2_kernel<<<NG, 64>>>(fc2_w, fc2_b);
    mlp3_kernel<<<NG, 32>>>(fc3_w, fc3_b, out);
}

// round 4
// speedup vs baseline: 1.3844x; 1.3844x over previous
#include <cuda_runtime.h>
#include <cuda_bf16.h>
#include <cstdint>

#define NN 20000
#define NE 320000
#define NG 256
#define DIM 256
#define NLAYER 4
#define EPS_BN 1e-5f
#define NB_STAT 157   // ceil(20000/128)

// ---------------- device scratch (static, no allocation) ----------------
__device__ __align__(16) float g_x[(size_t)NN * DIM];
__device__ __align__(16) float g_agg[(size_t)NN * DIM];
__device__ __align__(16) float g_h[(size_t)NN * DIM];
__device__ float g_invdeg[NN];
__device__ int   g_deg[NN];
__device__ int   g_fillpos[NN];
__device__ int   g_rowptr[NN + 1];
__device__ int   g_colidx[NE];
__device__ float g_psum[NB_STAT * DIM];
__device__ float g_psum2[NB_STAT * DIM];
__device__ float g_bn_a[DIM];
__device__ float g_bn_b[DIM];
__device__ int   g_gstart[NG + 1];
__device__ float g_pool[NG * DIM];
__device__ float g_mlp1[NG * 128];
__device__ float g_mlp2[NG * 64];
// transposed + bf16-split weights: [L][2(hi/lo)][256 n][512 k]
__device__ __align__(16) __nv_bfloat16 g_wt[(size_t)NLAYER * 2 * 256 * 512];

__device__ __forceinline__ uint32_t smem_u32(const void* p) {
    uint32_t a;
    asm("{ .reg .u64 t; cvta.to.shared.u64 t, %1; cvt.u32.u64 %0, t; }" : "=r"(a) : "l"(p));
    return a;
}

// ---------------- graph structure build ----------------
__global__ void zero_int_kernel() {
    int i = blockIdx.x * blockDim.x + threadIdx.x;
    if (i < NN) { g_deg[i] = 0; g_fillpos[i] = 0; }
}

__global__ void deg_kernel(const int* __restrict__ ei) {
    int e = blockIdx.x * blockDim.x + threadIdx.x;
    if (e >= NE) return;
    atomicAdd(&g_deg[ei[NE + e]], 1);
}

__global__ void invdeg_kernel() {
    int i = blockIdx.x * blockDim.x + threadIdx.x;
    if (i >= NN) return;
    int d = g_deg[i];
    g_invdeg[i] = (d > 0) ? 1.0f / (float)d : 0.0f;
}

// fast single-block scan: 512 threads x 40 elems, shuffle-based
__global__ void scan_kernel() {
    __shared__ int wsum[16];
    const int PER = 40;  // 512*40 = 20480 >= NN
    int tid = threadIdx.x;
    int i0 = tid * PER;
    int s = 0;
    for (int j = 0; j < PER; j++) {
        int i = i0 + j;
        if (i < NN) s += g_deg[i];
    }
    int lane = tid & 31, warp = tid >> 5;
    int inc = s;
    for (int off = 1; off < 32; off <<= 1) {
        int t = __shfl_up_sync(0xFFFFFFFFu, inc, off);
        if (lane >= off) inc += t;
    }
    if (lane == 31) wsum[warp] = inc;
    __syncthreads();
    if (warp == 0) {
        int v = (lane < 16) ? wsum[lane] : 0;
        for (int off = 1; off < 16; off <<= 1) {
            int t = __shfl_up_sync(0xFFFFFFFFu, v, off);
            if (lane >= off) v += t;
        }
        if (lane < 16) wsum[lane] = v;
    }
    __syncthreads();
    int prefix = inc - s + (warp > 0 ? wsum[warp - 1] : 0);  // exclusive
    int run = prefix;
    for (int j = 0; j < PER; j++) {
        int i = i0 + j;
        if (i < NN) { g_rowptr[i] = run; run += g_deg[i]; }
    }
    if (tid == 511) g_rowptr[NN] = run;
}

__global__ void fill_kernel(const int* __restrict__ ei) {
    int e = blockIdx.x * blockDim.x + threadIdx.x;
    if (e >= NE) return;
    int src = ei[e];
    int dst = ei[NE + e];
    int p = atomicAdd(&g_fillpos[dst], 1);
    g_colidx[g_rowptr[dst] + p] = src;
}

// sort each adjacency list (determinism of fp32 sum order)
__global__ void sort_adj_kernel() {
    int v = blockIdx.x * blockDim.x + threadIdx.x;
    if (v >= NN) return;
    int b = g_rowptr[v], e = g_rowptr[v + 1];
    for (int i = b + 1; i < e; i++) {
        int key = g_colidx[i];
        int j = i - 1;
        while (j >= b && g_colidx[j] > key) { g_colidx[j + 1] = g_colidx[j]; j--; }
        g_colidx[j + 1] = key;
    }
}

// ---------------- feature copy ----------------
__global__ void copy_x_kernel(const float* __restrict__ x) {
    size_t i = (size_t)(blockIdx.x * blockDim.x + threadIdx.x) * 4;
    if (i < (size_t)NN * DIM) {
        *(float4*)(g_x + i) = *(const float4*)(x + i);
    }
}

// ---------------- weight transpose + bf16 split ----------------
// g_wt[L][part][n][k], B[n][k] = W[k][n] ; k<256 -> Wl, else Wr
__global__ void wtconv_kernel(const float* __restrict__ Wl, const float* __restrict__ Wr) {
    __shared__ float t[32][33];
    int L = blockIdx.z, k0 = blockIdx.x * 32, n0 = blockIdx.y * 32;
    int tx = threadIdx.x, ty = threadIdx.y;
    const float* W = (k0 < 256) ? (Wl + (size_t)L * 65536 + (size_t)k0 * 256)
                                : (Wr + (size_t)L * 65536 + (size_t)(k0 - 256) * 256);
    t[ty][tx] = W[(size_t)ty * 256 + n0 + tx];
    __syncthreads();
    float v = t[tx][ty];  // = W[k0+tx][n0+ty]
    int n = n0 + ty, k = k0 + tx;
    __nv_bfloat16 hb = __float2bfloat16(v);
    __nv_bfloat16 lb = __float2bfloat16(v - __bfloat162float(hb));
    size_t base = (size_t)L * 262144;
    g_wt[base + (size_t)n * 512 + k] = hb;
    g_wt[base + 131072 + (size_t)n * 512 + k] = lb;
}

// ---------------- mean aggregation: warp per node ----------------
__global__ void gather_kernel() {
    int warp = (blockIdx.x * blockDim.x + threadIdx.x) >> 5;
    int lane = threadIdx.x & 31;
    if (warp >= NN) return;
    int b = g_rowptr[warp], e = g_rowptr[warp + 1];
    int col = lane * 8;
    float a0 = 0, a1 = 0, a2 = 0, a3 = 0, a4 = 0, a5 = 0, a6 = 0, a7 = 0;
    for (int j = b; j < e; j++) {
        int u = g_colidx[j];
        const float4* p = (const float4*)(g_x + (size_t)u * DIM + col);
        float4 x0 = p[0], x1 = p[1];
        a0 += x0.x; a1 += x0.y; a2 += x0.z; a3 += x0.w;
        a4 += x1.x; a5 += x1.y; a6 += x1.z; a7 += x1.w;
    }
    float s = g_invdeg[warp];
    float4* q = (float4*)(g_agg + (size_t)warp * DIM + col);
    q[0] = make_float4(a0 * s, a1 * s, a2 * s, a3 * s);
    q[1] = make_float4(a4 * s, a5 * s, a6 * s, a7 * s);
}

// ---------------- mma.sync bf16-split GEMM: h = [agg|x] @ [Wl;Wr] + bl ----------
// block 128(M) x 128(N), 8 warps each 64x32, K=512 in 16 chunks of 32.
// smem per stage (single buffer, 40960 B):
//   Ahi @0 (128 x 32 bf16, row stride 40 elems = 80 B), Alo @10240,
//   Bhi @20480 (128n x 32k), Blo @30720.
#define AHI 0
#define ALO 10240
#define BHI 20480
#define BLO 30720
#define GSM 40960

#define LDSM4(r, addr) \
    asm volatile("ldmatrix.sync.aligned.m8n8.x4.shared.b16 {%0,%1,%2,%3}, [%4];" \
        : "=r"((r)[0]), "=r"((r)[1]), "=r"((r)[2]), "=r"((r)[3]) : "r"(addr))

#define MMA16816(c, a, b0_, b1_) \
    asm volatile("mma.sync.aligned.m16n8k16.row.col.f32.bf16.bf16.f32 " \
        "{%0,%1,%2,%3}, {%4,%5,%6,%7}, {%8,%9}, {%0,%1,%2,%3};" \
        : "+f"((c)[0]), "+f"((c)[1]), "+f"((c)[2]), "+f"((c)[3]) \
        : "r"((a)[0]), "r"((a)[1]), "r"((a)[2]), "r"((a)[3]), "r"(b0_), "r"(b1_))

__device__ __forceinline__ void split_pair(float x, float y, uint32_t& h, uint32_t& l) {
    __nv_bfloat162 hb = __floats2bfloat162_rn(x, y);
    float hx = __low2float(hb), hy = __high2float(hb);
    __nv_bfloat162 lb = __floats2bfloat162_rn(x - hx, y - hy);
    h = *reinterpret_cast<uint32_t*>(&hb);
    l = *reinterpret_cast<uint32_t*>(&lb);
}

__global__ void __launch_bounds__(256, 2)
gemm_mma_kernel(int layer, const float* __restrict__ bl_) {
    extern __shared__ char sm[];
    uint32_t sb = smem_u32(sm);
    int tid = threadIdx.x;
    int lane = tid & 31, wid = tid >> 5;
    int wm = wid >> 2, wn = wid & 3;           // warp tile: 64(M) x 32(N)
    int m0 = blockIdx.x * 128, n0 = blockIdx.y * 128;
    const __nv_bfloat16* wtL = g_wt + (size_t)layer * 262144 + (size_t)n0 * 512;

    float C[4][4][4];
#pragma unroll
    for (int i = 0; i < 4; i++)
#pragma unroll
        for (int j = 0; j < 4; j++)
#pragma unroll
            for (int q = 0; q < 4; q++) C[i][j][q] = 0.0f;

    // ldmatrix per-lane address components (element units)
    uint32_t a_row = (uint32_t)(wm * 64 + (lane & 15));
    uint32_t a_koff = (uint32_t)((lane >> 4) * 8);
    uint32_t b_row = (uint32_t)(wn * 32 + ((lane >> 4) & 1) * 8 + (lane & 7));
    uint32_t b_koff = (uint32_t)(((lane >> 3) & 1) * 8);

    int am = tid >> 1, ahalf = tid & 1;        // A loader mapping
    int bp = tid >> 7, bn = tid & 127;         // B loader mapping

    for (int s = 0; s < 16; s++) {
        const float* Asrc = (s < 8) ? g_agg : g_x;
        int kg = (s & 7) * 32;
        __syncthreads();  // previous compute done, safe to overwrite smem
        // ---- A: 128 x 32 fp32 -> bf16 hi/lo ----
        {
            int gm = m0 + am;
            float4 av[4];
            if (gm < NN) {
                const float4* ap = (const float4*)(Asrc + (size_t)gm * 256 + kg + ahalf * 16);
#pragma unroll
                for (int i = 0; i < 4; i++) av[i] = ap[i];
            } else {
#pragma unroll
                for (int i = 0; i < 4; i++) av[i] = make_float4(0.f, 0.f, 0.f, 0.f);
            }
            uint32_t h[8], l[8];
#pragma unroll
            for (int i = 0; i < 4; i++) {
                split_pair(av[i].x, av[i].y, h[2 * i], l[2 * i]);
                split_pair(av[i].z, av[i].w, h[2 * i + 1], l[2 * i + 1]);
            }
            uint32_t off = (uint32_t)am * 80 + (uint32_t)ahalf * 32;
            *(uint4*)(sm + AHI + off)      = make_uint4(h[0], h[1], h[2], h[3]);
            *(uint4*)(sm + AHI + off + 16) = make_uint4(h[4], h[5], h[6], h[7]);
            *(uint4*)(sm + ALO + off)      = make_uint4(l[0], l[1], l[2], l[3]);
            *(uint4*)(sm + ALO + off + 16) = make_uint4(l[4], l[5], l[6], l[7]);
        }
        // ---- B: 128n x 32k bf16 (precomputed hi/lo) ----
        {
            const uint4* src = (const uint4*)(wtL + (size_t)bp * 131072 + (size_t)bn * 512 + s * 32);
            uint32_t off = (uint32_t)(BHI + bp * 10240) + (uint32_t)bn * 80;
#pragma unroll
            for (int i = 0; i < 4; i++) *(uint4*)(sm + off + i * 16) = src[i];
        }
        __syncthreads();
        // ---- compute: two k16 steps ----
#pragma unroll
        for (int kl = 0; kl < 32; kl += 16) {
            uint32_t bh[2][4], blo[2][4];
#pragma unroll
            for (int nf16 = 0; nf16 < 2; nf16++) {
                uint32_t ro = (b_row + nf16 * 16) * 80 + (b_koff + kl) * 2;
                LDSM4(bh[nf16], sb + BHI + ro);
                LDSM4(blo[nf16], sb + BLO + ro);
            }
#pragma unroll
            for (int mf = 0; mf < 4; mf++) {
                uint32_t ah[4], al[4];
                uint32_t ro = (a_row + mf * 16) * 80 + (a_koff + kl) * 2;
                LDSM4(ah, sb + AHI + ro);
                LDSM4(al, sb + ALO + ro);
#pragma unroll
                for (int nf = 0; nf < 4; nf++) {
                    uint32_t b0 = bh[nf >> 1][(nf & 1) * 2];
                    uint32_t b1 = bh[nf >> 1][(nf & 1) * 2 + 1];
                    uint32_t lb0 = blo[nf >> 1][(nf & 1) * 2];
                    uint32_t lb1 = blo[nf >> 1][(nf & 1) * 2 + 1];
                    MMA16816(C[mf][nf], ah, b0, b1);
                    MMA16816(C[mf][nf], al, b0, b1);
                    MMA16816(C[mf][nf], ah, lb0, lb1);
                }
            }
        }
    }
    // ---- epilogue: bias + store ----
    int mbase = m0 + wm * 64;
    int nbase = n0 + wn * 32;
#pragma unroll
    for (int mf = 0; mf < 4; mf++) {
#pragma unroll
        for (int nf = 0; nf < 4; nf++) {
            int c = nbase + nf * 8 + (lane & 3) * 2;
            float bv0 = bl_[c], bv1 = bl_[c + 1];
            int r0 = mbase + mf * 16 + (lane >> 2);
            if (r0 < NN) {
                float2 o = make_float2(C[mf][nf][0] + bv0, C[mf][nf][1] + bv1);
                *(float2*)(g_h + (size_t)r0 * 256 + c) = o;
            }
            int r1 = r0 + 8;
            if (r1 < NN) {
                float2 o = make_float2(C[mf][nf][2] + bv0, C[mf][nf][3] + bv1);
                *(float2*)(g_h + (size_t)r1 * 256 + c) = o;
            }
        }
    }
}

// ---------------- BatchNorm ----------------
__global__ void bn_stat_kernel() {
    int b = blockIdx.x;
    int d = threadIdx.x;
    int r0 = b * 128;
    int r1 = r0 + 128;
    if (r1 > NN) r1 = NN;
    float s = 0, s2 = 0;
    for (int r = r0; r < r1; r++) {
        float v = g_h[(size_t)r * DIM + d];
        s += v;
        s2 += v * v;
    }
    g_psum[b * DIM + d] = s;
    g_psum2[b * DIM + d] = s2;
}

__global__ void bn_reduce_kernel(const float* __restrict__ gamma, const float* __restrict__ beta) {
    int d = threadIdx.x;
    float s = 0, s2 = 0;
    for (int b = 0; b < NB_STAT; b++) {
        s += g_psum[b * DIM + d];
        s2 += g_psum2[b * DIM + d];
    }
    float mu = s / (float)NN;
    float var = s2 / (float)NN - mu * mu;
    float r = rsqrtf(var + EPS_BN);
    float a = gamma[d] * r;
    g_bn_a[d] = a;
    g_bn_b[d] = beta[d] - mu * a;
}

__global__ void bn_apply_kernel() {
    int row = blockIdx.x;
    int d = threadIdx.x;
    size_t idx = (size_t)row * DIM + d;
    float v = g_h[idx];
    g_x[idx] = fmaxf(v * g_bn_a[d] + g_bn_b[d], 0.0f);
}

// ---------------- pooling ----------------
__global__ void pool_bounds_kernel(const int* __restrict__ batch) {
    int g = threadIdx.x;
    if (g < NG) {
        int lo = 0, hi = NN;
        while (lo < hi) {
            int mid = (lo + hi) >> 1;
            if (batch[mid] < g) lo = mid + 1; else hi = mid;
        }
        g_gstart[g] = lo;
    }
    if (g == 0) g_gstart[NG] = NN;
}

__global__ void pool_kernel() {
    int g = blockIdx.x;
    int d = threadIdx.x;
    int r0 = g_gstart[g], r1 = g_gstart[g + 1];
    float s = 0;
    for (int r = r0; r < r1; r++) s += g_x[(size_t)r * DIM + d];
    int c = r1 - r0;
    g_pool[g * DIM + d] = s / (float)(c > 0 ? c : 1);
}

// ---------------- MLP ----------------
__global__ void mlp1_kernel(const float* __restrict__ w, const float* __restrict__ bias) {
    __shared__ float xr[256];
    int g = blockIdx.x, n = threadIdx.x;
    xr[n] = g_pool[g * 256 + n];
    xr[n + 128] = g_pool[g * 256 + n + 128];
    __syncthreads();
    float s = bias[n];
#pragma unroll 8
    for (int k = 0; k < 256; k++) s += xr[k] * w[k * 128 + n];
    g_mlp1[g * 128 + n] = fmaxf(s, 0.0f);
}

__global__ void mlp2_kernel(const float* __restrict__ w, const float* __restrict__ bias) {
    __shared__ float xr[128];
    int g = blockIdx.x, n = threadIdx.x;
    xr[n] = g_mlp1[g * 128 + n];
    xr[n + 64] = g_mlp1[g * 128 + n + 64];
    __syncthreads();
    float s = bias[n];
#pragma unroll 8
    for (int k = 0; k < 128; k++) s += xr[k] * w[k * 64 + n];
    g_mlp2[g * 64 + n] = fmaxf(s, 0.0f);
}

__global__ void mlp3_kernel(const float* __restrict__ w, const float* __restrict__ bias,
                            float* __restrict__ out) {
    __shared__ float xr[64];
    int g = blockIdx.x, n = threadIdx.x;
    if (n < 32) { xr[n] = g_mlp2[g * 64 + n]; xr[n + 32] = g_mlp2[g * 64 + n + 32]; }
    __syncthreads();
    if (n >= 10) return;
    float s = bias[n];
#pragma unroll 8
    for (int k = 0; k < 64; k++) s += xr[k] * w[k * 10 + n];
    out[g * 10 + n] = s;
}

// ---------------- host launch ----------------
extern "C" void kernel_launch(void* const* d_in, const int* in_sizes, int n_in,
                              void* d_out, int out_size) {
    const float* x     = (const float*)d_in[0];
    const int*   ei    = (const int*)d_in[1];
    const int*   batch = (const int*)d_in[2];
    const float* Wl    = (const float*)d_in[3];
    const float* bl    = (const float*)d_in[4];
    const float* Wr    = (const float*)d_in[5];
    const float* gamma = (const float*)d_in[6];
    const float* beta  = (const float*)d_in[7];
    const float* fc1_w = (const float*)d_in[8];
    const float* fc1_b = (const float*)d_in[9];
    const float* fc2_w = (const float*)d_in[10];
    const float* fc2_b = (const float*)d_in[11];
    const float* fc3_w = (const float*)d_in[12];
    const float* fc3_b = (const float*)d_in[13];
    float* out = (float*)d_out;

    // graph structure
    zero_int_kernel<<<(NN + 255) / 256, 256>>>();
    deg_kernel<<<(NE + 255) / 256, 256>>>(ei);
    invdeg_kernel<<<(NN + 255) / 256, 256>>>();
    scan_kernel<<<1, 512>>>();
    fill_kernel<<<(NE + 255) / 256, 256>>>(ei);
    sort_adj_kernel<<<(NN + 255) / 256, 256>>>();

    copy_x_kernel<<<(NN * DIM / 4 + 255) / 256, 256>>>(x);
    wtconv_kernel<<<dim3(16, 8, NLAYER), dim3(32, 32)>>>(Wl, Wr);

    for (int i = 0; i < NLAYER; i++) {
        gather_kernel<<<(NN * 32 + 255) / 256, 256>>>();
        gemm_mma_kernel<<<dim3((NN + 127) / 128, 2), 256, GSM>>>(i, bl + (size_t)i * DIM);
        bn_stat_kernel<<<NB_STAT, DIM>>>();
        bn_reduce_kernel<<<1, DIM>>>(gamma + (size_t)i * DIM, beta + (size_t)i * DIM);
        bn_apply_kernel<<<NN, DIM>>>();
    }

    pool_bounds_kernel<<<1, 256>>>(batch);
    pool_kernel<<<NG, DIM>>>();
    mlp1_kernel<<<NG, 128>>>(fc1_w, fc1_b);
    mlp2_kernel<<<NG, 64>>>(fc2_w, fc2_b);
    mlp3_kernel<<<NG, 32>>>(fc3_w, fc3_b, out);
}

// round 6
// speedup vs baseline: 1.6524x; 1.1936x over previous
#include <cuda_runtime.h>
#include <cuda_bf16.h>
#include <cstdint>

#define NN 20000
#define NE 320000
#define NG 256
#define DIM 256
#define NLAYER 4
#define EPS_BN 1e-5f
#define NB_STAT 157   // ceil(20000/128)

// ---------------- device scratch (static, no allocation) ----------------
__device__ __align__(16) float g_h[(size_t)NN * DIM];
__device__ __align__(16) __nv_bfloat16 g_xh[(size_t)NN * DIM];
__device__ __align__(16) __nv_bfloat16 g_xl[(size_t)NN * DIM];
__device__ __align__(16) __nv_bfloat16 g_aggh[(size_t)NN * DIM];
__device__ __align__(16) __nv_bfloat16 g_aggl[(size_t)NN * DIM];
__device__ float g_invdeg[NN];
__device__ int   g_deg[NN];
__device__ int   g_fillpos[NN];
__device__ int   g_rowptr[NN + 1];
__device__ int   g_colidx[NE];
__device__ float g_psum[NB_STAT * DIM];
__device__ float g_psum2[NB_STAT * DIM];
__device__ float g_bn_a[DIM];
__device__ float g_bn_b[DIM];
__device__ int   g_gstart[NG + 1];
__device__ float g_pool[NG * DIM];
__device__ float g_mlp1[NG * 128];
__device__ float g_mlp2[NG * 64];
// transposed + bf16-split weights: [L][2(hi/lo)][256 n][512 k]
__device__ __align__(16) __nv_bfloat16 g_wt[(size_t)NLAYER * 2 * 256 * 512];

__device__ __forceinline__ uint32_t smem_u32(const void* p) {
    uint32_t a;
    asm("{ .reg .u64 t; cvta.to.shared.u64 t, %1; cvt.u32.u64 %0, t; }" : "=r"(a) : "l"(p));
    return a;
}

__device__ __forceinline__ void split_pair(float x, float y, uint32_t& h, uint32_t& l) {
    __nv_bfloat162 hb = __floats2bfloat162_rn(x, y);
    float hx = __low2float(hb), hy = __high2float(hb);
    __nv_bfloat162 lb = __floats2bfloat162_rn(x - hx, y - hy);
    h = *reinterpret_cast<uint32_t*>(&hb);
    l = *reinterpret_cast<uint32_t*>(&lb);
}

// ---------------- graph structure build ----------------
__global__ void zero_int_kernel() {
    int i = blockIdx.x * blockDim.x + threadIdx.x;
    if (i < NN) { g_deg[i] = 0; g_fillpos[i] = 0; }
}

__global__ void deg_kernel(const int* __restrict__ ei) {
    int e = blockIdx.x * blockDim.x + threadIdx.x;
    if (e >= NE) return;
    atomicAdd(&g_deg[ei[NE + e]], 1);
}

__global__ void invdeg_kernel() {
    int i = blockIdx.x * blockDim.x + threadIdx.x;
    if (i >= NN) return;
    int d = g_deg[i];
    g_invdeg[i] = (d > 0) ? 1.0f / (float)d : 0.0f;
}

// single-block scan, smem-staged for coalescing
__global__ void scan_kernel() {
    extern __shared__ int sdeg[];
    __shared__ int wsum[16];
    int tid = threadIdx.x;
    for (int i = tid; i < NN; i += 512) sdeg[i] = g_deg[i];
    __syncthreads();
    const int PER = 40;  // 512*40 = 20480 >= NN
    int i0 = tid * PER;
    int s = 0;
    for (int j = 0; j < PER; j++) {
        int i = i0 + j;
        if (i < NN) s += sdeg[i];
    }
    int lane = tid & 31, warp = tid >> 5;
    int inc = s;
    for (int off = 1; off < 32; off <<= 1) {
        int t = __shfl_up_sync(0xFFFFFFFFu, inc, off);
        if (lane >= off) inc += t;
    }
    if (lane == 31) wsum[warp] = inc;
    __syncthreads();
    if (warp == 0) {
        int v = (lane < 16) ? wsum[lane] : 0;
        for (int off = 1; off < 16; off <<= 1) {
            int t = __shfl_up_sync(0xFFFFFFFFu, v, off);
            if (lane >= off) v += t;
        }
        if (lane < 16) wsum[lane] = v;
    }
    __syncthreads();
    int prefix = inc - s + (warp > 0 ? wsum[warp - 1] : 0);  // exclusive
    int run = prefix;
    for (int j = 0; j < PER; j++) {
        int i = i0 + j;
        if (i < NN) { int d = sdeg[i]; sdeg[i] = run; run += d; }
    }
    if (tid == 511) g_rowptr[NN] = run;
    __syncthreads();
    for (int i = tid; i < NN; i += 512) g_rowptr[i] = sdeg[i];
}

__global__ void fill_kernel(const int* __restrict__ ei) {
    int e = blockIdx.x * blockDim.x + threadIdx.x;
    if (e >= NE) return;
    int src = ei[e];
    int dst = ei[NE + e];
    int p = atomicAdd(&g_fillpos[dst], 1);
    g_colidx[g_rowptr[dst] + p] = src;
}

// sort each adjacency list (determinism of fp32 sum order)
__global__ void sort_adj_kernel() {
    int v = blockIdx.x * blockDim.x + threadIdx.x;
    if (v >= NN) return;
    int b = g_rowptr[v], e = g_rowptr[v + 1];
    for (int i = b + 1; i < e; i++) {
        int key = g_colidx[i];
        int j = i - 1;
        while (j >= b && g_colidx[j] > key) { g_colidx[j + 1] = g_colidx[j]; j--; }
        g_colidx[j + 1] = key;
    }
}

// ---------------- input conversion: x fp32 -> xh/xl bf16 split ----------------
__global__ void cvt_x_kernel(const float* __restrict__ x) {
    size_t e = (size_t)(blockIdx.x * blockDim.x + threadIdx.x) * 8;
    if (e >= (size_t)NN * DIM) return;
    float4 v0 = *(const float4*)(x + e);
    float4 v1 = *(const float4*)(x + e + 4);
    uint32_t h[4], l[4];
    split_pair(v0.x, v0.y, h[0], l[0]);
    split_pair(v0.z, v0.w, h[1], l[1]);
    split_pair(v1.x, v1.y, h[2], l[2]);
    split_pair(v1.z, v1.w, h[3], l[3]);
    *(uint4*)(g_xh + e) = make_uint4(h[0], h[1], h[2], h[3]);
    *(uint4*)(g_xl + e) = make_uint4(l[0], l[1], l[2], l[3]);
}

// ---------------- weight transpose + bf16 split ----------------
__global__ void wtconv_kernel(const float* __restrict__ Wl, const float* __restrict__ Wr) {
    __shared__ float t[32][33];
    int L = blockIdx.z, k0 = blockIdx.x * 32, n0 = blockIdx.y * 32;
    int tx = threadIdx.x, ty = threadIdx.y;
    const float* W = (k0 < 256) ? (Wl + (size_t)L * 65536 + (size_t)k0 * 256)
                                : (Wr + (size_t)L * 65536 + (size_t)(k0 - 256) * 256);
    t[ty][tx] = W[(size_t)ty * 256 + n0 + tx];
    __syncthreads();
    float v = t[tx][ty];  // = W[k0+tx][n0+ty]
    int n = n0 + ty, k = k0 + tx;
    __nv_bfloat16 hb = __float2bfloat16(v);
    __nv_bfloat16 lb = __float2bfloat16(v - __bfloat162float(hb));
    size_t base = (size_t)L * 262144;
    g_wt[base + (size_t)n * 512 + k] = hb;
    g_wt[base + 131072 + (size_t)n * 512 + k] = lb;
}

// ---------------- mean aggregation: warp per node, bf16-pair in/out ----------
__global__ void gather_kernel() {
    int warp = (blockIdx.x * blockDim.x + threadIdx.x) >> 5;
    int lane = threadIdx.x & 31;
    if (warp >= NN) return;
    int b = g_rowptr[warp], e = g_rowptr[warp + 1];
    int col = lane * 8;
    float a[8] = {0, 0, 0, 0, 0, 0, 0, 0};
    for (int j = b; j < e; j++) {
        int u = g_colidx[j];
        size_t off = (size_t)u * DIM + col;
        uint4 hq = *(const uint4*)(g_xh + off);
        uint4 lq = *(const uint4*)(g_xl + off);
        const __nv_bfloat162* hp = (const __nv_bfloat162*)&hq;
        const __nv_bfloat162* lp = (const __nv_bfloat162*)&lq;
#pragma unroll
        for (int q = 0; q < 4; q++) {
            float2 hf = __bfloat1622float2(hp[q]);
            float2 lf = __bfloat1622float2(lp[q]);
            a[2 * q] += hf.x + lf.x;
            a[2 * q + 1] += hf.y + lf.y;
        }
    }
    float s = g_invdeg[warp];
    uint32_t h[4], l[4];
#pragma unroll
    for (int q = 0; q < 4; q++) split_pair(a[2 * q] * s, a[2 * q + 1] * s, h[q], l[q]);
    size_t off = (size_t)warp * DIM + col;
    *(uint4*)(g_aggh + off) = make_uint4(h[0], h[1], h[2], h[3]);
    *(uint4*)(g_aggl + off) = make_uint4(l[0], l[1], l[2], l[3]);
}

// ---------------- pipelined mma.sync GEMM: h = [agg|x] @ [Wl;Wr] + bl --------
// block 128(M) x 128(N), 8 warps each 64x32, K=512 in 16 stages of 32.
// per stage (40960 B): Ahi@0 (128x32 bf16, row stride 80B), Alo@10240,
// Bhi@20480, Blo@30720. Two stages double-buffered via cp.async.
#define AHI 0
#define ALO 10240
#define BHI 20480
#define BLO 30720
#define STAGE 40960
#define GSM (2 * STAGE)

#define CPA(dst, src, sz) \
    asm volatile("cp.async.cg.shared.global [%0], [%1], 16, %2;" \
        :: "r"(dst), "l"(src), "r"(sz) : "memory")
#define CPC() asm volatile("cp.async.commit_group;" ::: "memory")
#define CPW(n) asm volatile("cp.async.wait_group %0;" :: "n"(n) : "memory")

#define LDSM4(r, addr) \
    asm volatile("ldmatrix.sync.aligned.m8n8.x4.shared.b16 {%0,%1,%2,%3}, [%4];" \
        : "=r"((r)[0]), "=r"((r)[1]), "=r"((r)[2]), "=r"((r)[3]) : "r"(addr))

#define MMA16816(c, a, b0_, b1_) \
    asm volatile("mma.sync.aligned.m16n8k16.row.col.f32.bf16.bf16.f32 " \
        "{%0,%1,%2,%3}, {%4,%5,%6,%7}, {%8,%9}, {%0,%1,%2,%3};" \
        : "+f"((c)[0]), "+f"((c)[1]), "+f"((c)[2]), "+f"((c)[3]) \
        : "r"((a)[0]), "r"((a)[1]), "r"((a)[2]), "r"((a)[3]), "r"(b0_), "r"(b1_))

__device__ __forceinline__ void load_stage(int s, uint32_t sb, int m0,
                                           const __nv_bfloat16* wtL) {
    const __nv_bfloat16* Ah = (s < 8) ? g_aggh : g_xh;
    const __nv_bfloat16* Al = (s < 8) ? g_aggl : g_xl;
    int kg = (s & 7) * 32;
    int tid = threadIdx.x;
#pragma unroll
    for (int i = 0; i < 2; i++) {
        int idx = tid + i * 256;
        int row = idx >> 2, q = idx & 3;
        int gm = m0 + row;
        uint32_t sz = (gm < NN) ? 16u : 0u;
        int gmc = (gm < NN) ? gm : 0;
        size_t so = (size_t)gmc * 256 + kg + q * 8;
        uint32_t off = (uint32_t)row * 80 + q * 16;
        CPA(sb + AHI + off, Ah + so, sz);
        CPA(sb + ALO + off, Al + so, sz);
    }
#pragma unroll
    for (int i = 0; i < 2; i++) {
        int idx = tid + i * 256;
        int row = idx >> 2, q = idx & 3;
        const __nv_bfloat16* src = wtL + (size_t)row * 512 + s * 32 + q * 8;
        uint32_t off = (uint32_t)row * 80 + q * 16;
        CPA(sb + BHI + off, src, 16u);
        CPA(sb + BLO + off, src + 131072, 16u);
    }
}

__global__ void __launch_bounds__(256, 2)
gemm_mma_kernel(int layer, const float* __restrict__ bl_) {
    extern __shared__ char sm[];
    uint32_t sb = smem_u32(sm);
    int tid = threadIdx.x;
    int lane = tid & 31, wid = tid >> 5;
    int wm = wid >> 2, wn = wid & 3;           // warp tile: 64(M) x 32(N)
    int m0 = blockIdx.x * 128, n0 = blockIdx.y * 128;
    const __nv_bfloat16* wtL = g_wt + (size_t)layer * 262144 + (size_t)n0 * 512;

    float C[4][4][4];
#pragma unroll
    for (int i = 0; i < 4; i++)
#pragma unroll
        for (int j = 0; j < 4; j++)
#pragma unroll
            for (int q = 0; q < 4; q++) C[i][j][q] = 0.0f;

    uint32_t a_row = (uint32_t)(wm * 64 + (lane & 15));
    uint32_t a_koff = (uint32_t)((lane >> 4) * 8);
    uint32_t b_row = (uint32_t)(wn * 32 + ((lane >> 4) & 1) * 8 + (lane & 7));
    uint32_t b_koff = (uint32_t)(((lane >> 3) & 1) * 8);

    load_stage(0, sb, m0, wtL);
    CPC();

    for (int s = 0; s < 16; s++) {
        if (s < 15) {
            load_stage(s + 1, sb + ((uint32_t)(s + 1) & 1u) * STAGE, m0, wtL);
            CPC();
            CPW(1);
        } else {
            CPW(0);
        }
        __syncthreads();
        uint32_t bufb = sb + ((uint32_t)s & 1u) * STAGE;
#pragma unroll
        for (int kl = 0; kl < 32; kl += 16) {
            uint32_t bh[2][4], blo_[2][4];
#pragma unroll
            for (int nf16 = 0; nf16 < 2; nf16++) {
                uint32_t ro = (b_row + nf16 * 16) * 80 + (b_koff + kl) * 2;
                LDSM4(bh[nf16], bufb + BHI + ro);
                LDSM4(blo_[nf16], bufb + BLO + ro);
            }
#pragma unroll
            for (int mf = 0; mf < 4; mf++) {
                uint32_t ah[4], al[4];
                uint32_t ro = (a_row + mf * 16) * 80 + (a_koff + kl) * 2;
                LDSM4(ah, bufb + AHI + ro);
                LDSM4(al, bufb + ALO + ro);
#pragma unroll
                for (int nf = 0; nf < 4; nf++) {
                    uint32_t b0 = bh[nf >> 1][(nf & 1) * 2];
                    uint32_t b1 = bh[nf >> 1][(nf & 1) * 2 + 1];
                    uint32_t lb0 = blo_[nf >> 1][(nf & 1) * 2];
                    uint32_t lb1 = blo_[nf >> 1][(nf & 1) * 2 + 1];
                    MMA16816(C[mf][nf], ah, b0, b1);
                    MMA16816(C[mf][nf], al, b0, b1);
                    MMA16816(C[mf][nf], ah, lb0, lb1);
                }
            }
        }
        __syncthreads();
    }
    // ---- epilogue: bias + store ----
    int mbase = m0 + wm * 64;
    int nbase = n0 + wn * 32;
#pragma unroll
    for (int mf = 0; mf < 4; mf++) {
#pragma unroll
        for (int nf = 0; nf < 4; nf++) {
            int c = nbase + nf * 8 + (lane & 3) * 2;
            float bv0 = bl_[c], bv1 = bl_[c + 1];
            int r0 = mbase + mf * 16 + (lane >> 2);
            if (r0 < NN) {
                float2 o = make_float2(C[mf][nf][0] + bv0, C[mf][nf][1] + bv1);
                *(float2*)(g_h + (size_t)r0 * 256 + c) = o;
            }
            int r1 = r0 + 8;
            if (r1 < NN) {
                float2 o = make_float2(C[mf][nf][2] + bv0, C[mf][nf][3] + bv1);
                *(float2*)(g_h + (size_t)r1 * 256 + c) = o;
            }
        }
    }
}

// ---------------- BatchNorm ----------------
__global__ void bn_stat_kernel() {
    int b = blockIdx.x;
    int d = threadIdx.x;
    int r0 = b * 128;
    int r1 = r0 + 128;
    if (r1 > NN) r1 = NN;
    float s = 0, s2 = 0;
    for (int r = r0; r < r1; r++) {
        float v = g_h[(size_t)r * DIM + d];
        s += v;
        s2 += v * v;
    }
    g_psum[b * DIM + d] = s;
    g_psum2[b * DIM + d] = s2;
}

__global__ void bn_reduce_kernel(const float* __restrict__ gamma, const float* __restrict__ beta) {
    int d = threadIdx.x;
    float s = 0, s2 = 0;
    for (int b = 0; b < NB_STAT; b++) {
        s += g_psum[b * DIM + d];
        s2 += g_psum2[b * DIM + d];
    }
    float mu = s / (float)NN;
    float var = s2 / (float)NN - mu * mu;
    float r = rsqrtf(var + EPS_BN);
    float a = gamma[d] * r;
    g_bn_a[d] = a;
    g_bn_b[d] = beta[d] - mu * a;
}

// relu(bn(h)) -> bf16 hi/lo split
__global__ void bnapply_kernel() {
    size_t e = (size_t)(blockIdx.x * blockDim.x + threadIdx.x) * 8;
    if (e >= (size_t)NN * DIM) return;
    int d = (int)(e & 255u);
    float4 v0 = *(const float4*)(g_h + e);
    float4 v1 = *(const float4*)(g_h + e + 4);
    float4 a0 = *(const float4*)(g_bn_a + d);
    float4 a1 = *(const float4*)(g_bn_a + d + 4);
    float4 b0 = *(const float4*)(g_bn_b + d);
    float4 b1 = *(const float4*)(g_bn_b + d + 4);
    float y[8];
    y[0] = fmaxf(v0.x * a0.x + b0.x, 0.f);
    y[1] = fmaxf(v0.y * a0.y + b0.y, 0.f);
    y[2] = fmaxf(v0.z * a0.z + b0.z, 0.f);
    y[3] = fmaxf(v0.w * a0.w + b0.w, 0.f);
    y[4] = fmaxf(v1.x * a1.x + b1.x, 0.f);
    y[5] = fmaxf(v1.y * a1.y + b1.y, 0.f);
    y[6] = fmaxf(v1.z * a1.z + b1.z, 0.f);
    y[7] = fmaxf(v1.w * a1.w + b1.w, 0.f);
    uint32_t h[4], l[4];
#pragma unroll
    for (int q = 0; q < 4; q++) split_pair(y[2 * q], y[2 * q + 1], h[q], l[q]);
    *(uint4*)(g_xh + e) = make_uint4(h[0], h[1], h[2], h[3]);
    *(uint4*)(g_xl + e) = make_uint4(l[0], l[1], l[2], l[3]);
}

// ---------------- pooling ----------------
__global__ void pool_bounds_kernel(const int* __restrict__ batch) {
    int g = threadIdx.x;
    if (g < NG) {
        int lo = 0, hi = NN;
        while (lo < hi) {
            int mid = (lo + hi) >> 1;
            if (batch[mid] < g) lo = mid + 1; else hi = mid;
        }
        g_gstart[g] = lo;
    }
    if (g == 0) g_gstart[NG] = NN;
}

__global__ void pool_kernel() {
    int g = blockIdx.x;
    int d = threadIdx.x;
    int r0 = g_gstart[g], r1 = g_gstart[g + 1];
    float s = 0;
    for (int r = r0; r < r1; r++) {
        size_t off = (size_t)r * DIM + d;
        s += __bfloat162float(g_xh[off]) + __bfloat162float(g_xl[off]);
    }
    int c = r1 - r0;
    g_pool[g * DIM + d] = s / (float)(c > 0 ? c : 1);
}

// ---------------- MLP ----------------
__global__ void mlp1_kernel(const float* __restrict__ w, const float* __restrict__ bias) {
    __shared__ float xr[256];
    int g = blockIdx.x, n = threadIdx.x;
    xr[n] = g_pool[g * 256 + n];
    xr[n + 128] = g_pool[g * 256 + n + 128];
    __syncthreads();
    float s = bias[n];
#pragma unroll 8
    for (int k = 0; k < 256; k++) s += xr[k] * w[k * 128 + n];
    g_mlp1[g * 128 + n] = fmaxf(s, 0.0f);
}

__global__ void mlp2_kernel(const float* __restrict__ w, const float* __restrict__ bias) {
    __shared__ float xr[128];
    int g = blockIdx.x, n = threadIdx.x;
    xr[n] = g_mlp1[g * 128 + n];
    xr[n + 64] = g_mlp1[g * 128 + n + 64];
    __syncthreads();
    float s = bias[n];
#pragma unroll 8
    for (int k = 0; k < 128; k++) s += xr[k] * w[k * 64 + n];
    g_mlp2[g * 64 + n] = fmaxf(s, 0.0f);
}

__global__ void mlp3_kernel(const float* __restrict__ w, const float* __restrict__ bias,
                            float* __restrict__ out) {
    __shared__ float xr[64];
    int g = blockIdx.x, n = threadIdx.x;
    if (n < 32) { xr[n] = g_mlp2[g * 64 + n]; xr[n + 32] = g_mlp2[g * 64 + n + 32]; }
    __syncthreads();
    if (n >= 10) return;
    float s = bias[n];
#pragma unroll 8
    for (int k = 0; k < 64; k++) s += xr[k] * w[k * 10 + n];
    out[g * 10 + n] = s;
}

// ---------------- host launch ----------------
extern "C" void kernel_launch(void* const* d_in, const int* in_sizes, int n_in,
                              void* d_out, int out_size) {
    const float* x     = (const float*)d_in[0];
    const int*   ei    = (const int*)d_in[1];
    const int*   batch = (const int*)d_in[2];
    const float* Wl    = (const float*)d_in[3];
    const float* bl    = (const float*)d_in[4];
    const float* Wr    = (const float*)d_in[5];
    const float* gamma = (const float*)d_in[6];
    const float* beta  = (const float*)d_in[7];
    const float* fc1_w = (const float*)d_in[8];
    const float* fc1_b = (const float*)d_in[9];
    const float* fc2_w = (const float*)d_in[10];
    const float* fc2_b = (const float*)d_in[11];
    const float* fc3_w = (const float*)d_in[12];
    const float* fc3_b = (const float*)d_in[13];
    float* out = (float*)d_out;

    static bool attr_set = false;
    if (!attr_set) {
        cudaFuncSetAttribute(gemm_mma_kernel, cudaFuncAttributeMaxDynamicSharedMemorySize, GSM);
        cudaFuncSetAttribute(scan_kernel, cudaFuncAttributeMaxDynamicSharedMemorySize, NN * 4);
        attr_set = true;
    }

    // graph structure
    zero_int_kernel<<<(NN + 255) / 256, 256>>>();
    deg_kernel<<<(NE + 255) / 256, 256>>>(ei);
    invdeg_kernel<<<(NN + 255) / 256, 256>>>();
    scan_kernel<<<1, 512, NN * 4>>>();
    fill_kernel<<<(NE + 255) / 256, 256>>>(ei);
    sort_adj_kernel<<<(NN + 255) / 256, 256>>>();

    cvt_x_kernel<<<(NN * DIM / 8 + 255) / 256, 256>>>(x);
    wtconv_kernel<<<dim3(16, 8, NLAYER), dim3(32, 32)>>>(Wl, Wr);

    for (int i = 0; i < NLAYER; i++) {
        gather_kernel<<<(NN * 32 + 255) / 256, 256>>>();
        gemm_mma_kernel<<<dim3((NN + 127) / 128, 2), 256, GSM>>>(i, bl + (size_t)i * DIM);
        bn_stat_kernel<<<NB_STAT, DIM>>>();
        bn_reduce_kernel<<<1, DIM>>>(gamma + (size_t)i * DIM, beta + (size_t)i * DIM);
        bnapply_kernel<<<(NN * DIM / 8 + 255) / 256, 256>>>();
    }

    pool_bounds_kernel<<<1, 256>>>(batch);
    pool_kernel<<<NG, DIM>>>();
    mlp1_kernel<<<NG, 128>>>(fc1_w, fc1_b);
    mlp2_kernel<<<NG, 64>>>(fc2_w, fc2_b);
    mlp3_kernel<<<NG, 32>>>(fc3_w, fc3_b, out);
}

// round 8
// speedup vs baseline: 1.7076x; 1.0334x over previous
#include <cuda_runtime.h>
#include <cuda_bf16.h>
#include <cstdint>

#define NN 20000
#define NE 320000
#define NG 256
#define DIM 256
#define NLAYER 4
#define EPS_BN 1e-5f
#define NB_STAT 157   // ceil(20000/128) = gemm grid.x

// ---------------- device scratch (static, no allocation) ----------------
__device__ __align__(16) float g_h[(size_t)NN * DIM];
__device__ __align__(16) __nv_bfloat16 g_xh[(size_t)NN * DIM];
__device__ __align__(16) __nv_bfloat16 g_xl[(size_t)NN * DIM];
__device__ __align__(16) __nv_bfloat16 g_aggh[(size_t)NN * DIM];
__device__ __align__(16) __nv_bfloat16 g_aggl[(size_t)NN * DIM];
__device__ float g_invdeg[NN];
__device__ int   g_deg[NN];
__device__ int   g_fillpos[NN];
__device__ int   g_rowptr[NN + 1];
__device__ int   g_colidx[NE];
__device__ float g_psum[NB_STAT * DIM];
__device__ float g_psum2[NB_STAT * DIM];
__device__ float g_bn_a[DIM];
__device__ float g_bn_b[DIM];
__device__ int   g_gstart[NG + 1];
__device__ float g_pool[NG * DIM];
__device__ float g_mlp1[NG * 128];
__device__ float g_mlp2[NG * 64];
// transposed + bf16-split weights: [L][2(hi/lo)][256 n][512 k]
__device__ __align__(16) __nv_bfloat16 g_wt[(size_t)NLAYER * 2 * 256 * 512];

__device__ __forceinline__ uint32_t smem_u32(const void* p) {
    uint32_t a;
    asm("{ .reg .u64 t; cvta.to.shared.u64 t, %1; cvt.u32.u64 %0, t; }" : "=r"(a) : "l"(p));
    return a;
}

__device__ __forceinline__ void split_pair(float x, float y, uint32_t& h, uint32_t& l) {
    __nv_bfloat162 hb = __floats2bfloat162_rn(x, y);
    float hx = __low2float(hb), hy = __high2float(hb);
    __nv_bfloat162 lb = __floats2bfloat162_rn(x - hx, y - hy);
    h = *reinterpret_cast<uint32_t*>(&hb);
    l = *reinterpret_cast<uint32_t*>(&lb);
}

// ---------------- graph structure build ----------------
__global__ void zero_int_kernel() {
    int i = blockIdx.x * blockDim.x + threadIdx.x;
    if (i < NN) { g_deg[i] = 0; g_fillpos[i] = 0; }
}

__global__ void deg_kernel(const int* __restrict__ ei) {
    int e = blockIdx.x * blockDim.x + threadIdx.x;
    if (e >= NE) return;
    atomicAdd(&g_deg[ei[NE + e]], 1);
}

// single-block scan (smem-staged), also emits invdeg
__global__ void scan_kernel() {
    extern __shared__ int sdeg[];
    __shared__ int wsum[16];
    int tid = threadIdx.x;
    for (int i = tid; i < NN; i += 512) {
        int d = g_deg[i];
        sdeg[i] = d;
        g_invdeg[i] = (d > 0) ? 1.0f / (float)d : 0.0f;
    }
    __syncthreads();
    const int PER = 40;  // 512*40 = 20480 >= NN
    int i0 = tid * PER;
    int s = 0;
    for (int j = 0; j < PER; j++) {
        int i = i0 + j;
        if (i < NN) s += sdeg[i];
    }
    int lane = tid & 31, warp = tid >> 5;
    int inc = s;
    for (int off = 1; off < 32; off <<= 1) {
        int t = __shfl_up_sync(0xFFFFFFFFu, inc, off);
        if (lane >= off) inc += t;
    }
    if (lane == 31) wsum[warp] = inc;
    __syncthreads();
    if (warp == 0) {
        int v = (lane < 16) ? wsum[lane] : 0;
        for (int off = 1; off < 16; off <<= 1) {
            int t = __shfl_up_sync(0xFFFFFFFFu, v, off);
            if (lane >= off) v += t;
        }
        if (lane < 16) wsum[lane] = v;
    }
    __syncthreads();
    int prefix = inc - s + (warp > 0 ? wsum[warp - 1] : 0);  // exclusive
    int run = prefix;
    for (int j = 0; j < PER; j++) {
        int i = i0 + j;
        if (i < NN) { int d = sdeg[i]; sdeg[i] = run; run += d; }
    }
    if (tid == 511) g_rowptr[NN] = run;
    __syncthreads();
    for (int i = tid; i < NN; i += 512) g_rowptr[i] = sdeg[i];
}

__global__ void fill_kernel(const int* __restrict__ ei) {
    int e = blockIdx.x * blockDim.x + threadIdx.x;
    if (e >= NE) return;
    int src = ei[e];
    int dst = ei[NE + e];
    int p = atomicAdd(&g_fillpos[dst], 1);
    g_colidx[g_rowptr[dst] + p] = src;
}

// sort each adjacency list (determinism of fp32 sum order)
__global__ void sort_adj_kernel() {
    int v = blockIdx.x * blockDim.x + threadIdx.x;
    if (v >= NN) return;
    int b = g_rowptr[v], e = g_rowptr[v + 1];
    for (int i = b + 1; i < e; i++) {
        int key = g_colidx[i];
        int j = i - 1;
        while (j >= b && g_colidx[j] > key) { g_colidx[j + 1] = g_colidx[j]; j--; }
        g_colidx[j + 1] = key;
    }
}

// ---------------- input conversion: x fp32 -> xh/xl bf16 split ----------------
__global__ void cvt_x_kernel(const float* __restrict__ x) {
    size_t e = (size_t)(blockIdx.x * blockDim.x + threadIdx.x) * 8;
    if (e >= (size_t)NN * DIM) return;
    float4 v0 = *(const float4*)(x + e);
    float4 v1 = *(const float4*)(x + e + 4);
    uint32_t h[4], l[4];
    split_pair(v0.x, v0.y, h[0], l[0]);
    split_pair(v0.z, v0.w, h[1], l[1]);
    split_pair(v1.x, v1.y, h[2], l[2]);
    split_pair(v1.z, v1.w, h[3], l[3]);
    *(uint4*)(g_xh + e) = make_uint4(h[0], h[1], h[2], h[3]);
    *(uint4*)(g_xl + e) = make_uint4(l[0], l[1], l[2], l[3]);
}

// ---------------- weight transpose + bf16 split ----------------
__global__ void wtconv_kernel(const float* __restrict__ Wl, const float* __restrict__ Wr) {
    __shared__ float t[32][33];
    int L = blockIdx.z, k0 = blockIdx.x * 32, n0 = blockIdx.y * 32;
    int tx = threadIdx.x, ty = threadIdx.y;
    const float* W = (k0 < 256) ? (Wl + (size_t)L * 65536 + (size_t)k0 * 256)
                                : (Wr + (size_t)L * 65536 + (size_t)(k0 - 256) * 256);
    t[ty][tx] = W[(size_t)ty * 256 + n0 + tx];
    __syncthreads();
    float v = t[tx][ty];  // = W[k0+tx][n0+ty]
    int n = n0 + ty, k = k0 + tx;
    __nv_bfloat16 hb = __float2bfloat16(v);
    __nv_bfloat16 lb = __float2bfloat16(v - __bfloat162float(hb));
    size_t base = (size_t)L * 262144;
    g_wt[base + (size_t)n * 512 + k] = hb;
    g_wt[base + 131072 + (size_t)n * 512 + k] = lb;
}

// ---------------- mean aggregation: warp per node, bf16-pair in/out ----------
__global__ void gather_kernel() {
    int warp = (blockIdx.x * blockDim.x + threadIdx.x) >> 5;
    int lane = threadIdx.x & 31;
    if (warp >= NN) return;
    int b = g_rowptr[warp], e = g_rowptr[warp + 1];
    int col = lane * 8;
    float a[8] = {0, 0, 0, 0, 0, 0, 0, 0};
    for (int j = b; j < e; j++) {
        int u = g_colidx[j];
        size_t off = (size_t)u * DIM + col;
        uint4 hq = *(const uint4*)(g_xh + off);
        uint4 lq = *(const uint4*)(g_xl + off);
        const __nv_bfloat162* hp = (const __nv_bfloat162*)&hq;
        const __nv_bfloat162* lp = (const __nv_bfloat162*)&lq;
#pragma unroll
        for (int q = 0; q < 4; q++) {
            float2 hf = __bfloat1622float2(hp[q]);
            float2 lf = __bfloat1622float2(lp[q]);
            a[2 * q] += hf.x + lf.x;
            a[2 * q + 1] += hf.y + lf.y;
        }
    }
    float s = g_invdeg[warp];
    uint32_t h[4], l[4];
#pragma unroll
    for (int q = 0; q < 4; q++) split_pair(a[2 * q] * s, a[2 * q + 1] * s, h[q], l[q]);
    size_t off = (size_t)warp * DIM + col;
    *(uint4*)(g_aggh + off) = make_uint4(h[0], h[1], h[2], h[3]);
    *(uint4*)(g_aggl + off) = make_uint4(l[0], l[1], l[2], l[3]);
}

// ---------------- pipelined mma.sync GEMM + fused BN stats -------------------
// block 128(M) x 128(N), 8 warps each 64x32, K=512 in 16 stages of 32.
// per stage (40960 B): Ahi@0 (128x32 bf16, row stride 80B), Alo@10240,
// Bhi@20480, Blo@30720. Two stages double-buffered via cp.async.
#define AHI 0
#define ALO 10240
#define BHI 20480
#define BLO 30720
#define STAGE 40960
#define GSM (2 * STAGE)

#define CPA(dst, src, sz) \
    asm volatile("cp.async.cg.shared.global [%0], [%1], 16, %2;" \
        :: "r"(dst), "l"(src), "r"(sz) : "memory")
#define CPC() asm volatile("cp.async.commit_group;" ::: "memory")
#define CPW(n) asm volatile("cp.async.wait_group %0;" :: "n"(n) : "memory")

#define LDSM4(r, addr) \
    asm volatile("ldmatrix.sync.aligned.m8n8.x4.shared.b16 {%0,%1,%2,%3}, [%4];" \
        : "=r"((r)[0]), "=r"((r)[1]), "=r"((r)[2]), "=r"((r)[3]) : "r"(addr))

#define MMA16816(c, a, b0_, b1_) \
    asm volatile("mma.sync.aligned.m16n8k16.row.col.f32.bf16.bf16.f32 " \
        "{%0,%1,%2,%3}, {%4,%5,%6,%7}, {%8,%9}, {%0,%1,%2,%3};" \
        : "+f"((c)[0]), "+f"((c)[1]), "+f"((c)[2]), "+f"((c)[3]) \
        : "r"((a)[0]), "r"((a)[1]), "r"((a)[2]), "r"((a)[3]), "r"(b0_), "r"(b1_))

__device__ __forceinline__ void load_stage(int s, uint32_t sb, int m0,
                                           const __nv_bfloat16* wtL) {
    const __nv_bfloat16* Ah = (s < 8) ? g_aggh : g_xh;
    const __nv_bfloat16* Al = (s < 8) ? g_aggl : g_xl;
    int kg = (s & 7) * 32;
    int tid = threadIdx.x;
#pragma unroll
    for (int i = 0; i < 2; i++) {
        int idx = tid + i * 256;
        int row = idx >> 2, q = idx & 3;
        int gm = m0 + row;
        uint32_t sz = (gm < NN) ? 16u : 0u;
        int gmc = (gm < NN) ? gm : 0;
        size_t so = (size_t)gmc * 256 + kg + q * 8;
        uint32_t off = (uint32_t)row * 80 + q * 16;
        CPA(sb + AHI + off, Ah + so, sz);
        CPA(sb + ALO + off, Al + so, sz);
    }
#pragma unroll
    for (int i = 0; i < 2; i++) {
        int idx = tid + i * 256;
        int row = idx >> 2, q = idx & 3;
        const __nv_bfloat16* src = wtL + (size_t)row * 512 + s * 32 + q * 8;
        uint32_t off = (uint32_t)row * 80 + q * 16;
        CPA(sb + BHI + off, src, 16u);
        CPA(sb + BLO + off, src + 131072, 16u);
    }
}

__global__ void __launch_bounds__(256, 2)
gemm_mma_kernel(int layer, const float* __restrict__ bl_) {
    extern __shared__ char sm[];
    __shared__ float sred[2][128][2];  // [wm][local col][{sum, sumsq}]
    uint32_t sb = smem_u32(sm);
    int tid = threadIdx.x;
    int lane = tid & 31, wid = tid >> 5;
    int wm = wid >> 2, wn = wid & 3;           // warp tile: 64(M) x 32(N)
    int m0 = blockIdx.x * 128, n0 = blockIdx.y * 128;
    const __nv_bfloat16* wtL = g_wt + (size_t)layer * 262144 + (size_t)n0 * 512;

    float C[4][4][4];
#pragma unroll
    for (int i = 0; i < 4; i++)
#pragma unroll
        for (int j = 0; j < 4; j++)
#pragma unroll
            for (int q = 0; q < 4; q++) C[i][j][q] = 0.0f;

    uint32_t a_row = (uint32_t)(wm * 64 + (lane & 15));
    uint32_t a_koff = (uint32_t)((lane >> 4) * 8);
    uint32_t b_row = (uint32_t)(wn * 32 + ((lane >> 4) & 1) * 8 + (lane & 7));
    uint32_t b_koff = (uint32_t)(((lane >> 3) & 1) * 8);

    load_stage(0, sb, m0, wtL);
    CPC();

    for (int s = 0; s < 16; s++) {
        if (s < 15) {
            load_stage(s + 1, sb + ((uint32_t)(s + 1) & 1u) * STAGE, m0, wtL);
            CPC();
            CPW(1);
        } else {
            CPW(0);
        }
        __syncthreads();
        uint32_t bufb = sb + ((uint32_t)s & 1u) * STAGE;
#pragma unroll
        for (int kl = 0; kl < 32; kl += 16) {
            uint32_t bh[2][4], blo_[2][4];
#pragma unroll
            for (int nf16 = 0; nf16 < 2; nf16++) {
                uint32_t ro = (b_row + nf16 * 16) * 80 + (b_koff + kl) * 2;
                LDSM4(bh[nf16], bufb + BHI + ro);
                LDSM4(blo_[nf16], bufb + BLO + ro);
            }
#pragma unroll
            for (int mf = 0; mf < 4; mf++) {
                uint32_t ah[4], al[4];
                uint32_t ro = (a_row + mf * 16) * 80 + (a_koff + kl) * 2;
                LDSM4(ah, bufb + AHI + ro);
                LDSM4(al, bufb + ALO + ro);
#pragma unroll
                for (int nf = 0; nf < 4; nf++) {
                    uint32_t b0 = bh[nf >> 1][(nf & 1) * 2];
                    uint32_t b1 = bh[nf >> 1][(nf & 1) * 2 + 1];
                    uint32_t lb0 = blo_[nf >> 1][(nf & 1) * 2];
                    uint32_t lb1 = blo_[nf >> 1][(nf & 1) * 2 + 1];
                    MMA16816(C[mf][nf], ah, b0, b1);
                    MMA16816(C[mf][nf], al, b0, b1);
                    MMA16816(C[mf][nf], ah, lb0, lb1);
                }
            }
        }
        __syncthreads();
    }
    // ---- epilogue: bias + store + fused BN stats ----
    int mbase = m0 + wm * 64;
    int nbase = n0 + wn * 32;
    float ts[4][2], ts2[4][2];
#pragma unroll
    for (int nf = 0; nf < 4; nf++) {
        ts[nf][0] = ts[nf][1] = 0.f;
        ts2[nf][0] = ts2[nf][1] = 0.f;
    }
#pragma unroll
    for (int mf = 0; mf < 4; mf++) {
#pragma unroll
        for (int nf = 0; nf < 4; nf++) {
            int c = nbase + nf * 8 + (lane & 3) * 2;
            float bv0 = bl_[c], bv1 = bl_[c + 1];
            int r0 = mbase + mf * 16 + (lane >> 2);
            if (r0 < NN) {
                float ox = C[mf][nf][0] + bv0, oy = C[mf][nf][1] + bv1;
                *(float2*)(g_h + (size_t)r0 * 256 + c) = make_float2(ox, oy);
                ts[nf][0] += ox; ts2[nf][0] += ox * ox;
                ts[nf][1] += oy; ts2[nf][1] += oy * oy;
            }
            int r1 = r0 + 8;
            if (r1 < NN) {
                float ox = C[mf][nf][2] + bv0, oy = C[mf][nf][3] + bv1;
                *(float2*)(g_h + (size_t)r1 * 256 + c) = make_float2(ox, oy);
                ts[nf][0] += ox; ts2[nf][0] += ox * ox;
                ts[nf][1] += oy; ts2[nf][1] += oy * oy;
            }
        }
    }
    // reduce across the 8 lanes sharing each column (lane>>2 varies, lane&3 fixed)
#pragma unroll
    for (int nf = 0; nf < 4; nf++) {
#pragma unroll
        for (int i = 0; i < 2; i++) {
#pragma unroll
            for (int msk = 4; msk < 32; msk <<= 1) {
                ts[nf][i] += __shfl_xor_sync(0xFFFFFFFFu, ts[nf][i], msk);
                ts2[nf][i] += __shfl_xor_sync(0xFFFFFFFFu, ts2[nf][i], msk);
            }
        }
    }
    if (lane < 4) {
#pragma unroll
        for (int nf = 0; nf < 4; nf++) {
            int coll = wn * 32 + nf * 8 + lane * 2;
            sred[wm][coll][0] = ts[nf][0];
            sred[wm][coll][1] = ts2[nf][0];
            sred[wm][coll + 1][0] = ts[nf][1];
            sred[wm][coll + 1][1] = ts2[nf][1];
        }
    }
    __syncthreads();
    if (tid < 128) {
        float s = sred[0][tid][0] + sred[1][tid][0];
        float s2 = sred[0][tid][1] + sred[1][tid][1];
        int cg = blockIdx.x * 256 + n0 + tid;
        g_psum[cg] = s;
        g_psum2[cg] = s2;
    }
}

// ---------------- BatchNorm reduce (tiny) ----------------
__global__ void bn_reduce_kernel(const float* __restrict__ gamma, const float* __restrict__ beta) {
    int d = threadIdx.x;
    float s = 0, s2 = 0;
    for (int b = 0; b < NB_STAT; b++) {
        s += g_psum[b * DIM + d];
        s2 += g_psum2[b * DIM + d];
    }
    float mu = s / (float)NN;
    float var = s2 / (float)NN - mu * mu;
    float r = rsqrtf(var + EPS_BN);
    float a = gamma[d] * r;
    g_bn_a[d] = a;
    g_bn_b[d] = beta[d] - mu * a;
}

// relu(bn(h)) -> bf16 hi/lo split
__global__ void bnapply_kernel() {
    size_t e = (size_t)(blockIdx.x * blockDim.x + threadIdx.x) * 8;
    if (e >= (size_t)NN * DIM) return;
    int d = (int)(e & 255u);
    float4 v0 = *(const float4*)(g_h + e);
    float4 v1 = *(const float4*)(g_h + e + 4);
    float4 a0 = *(const float4*)(g_bn_a + d);
    float4 a1 = *(const float4*)(g_bn_a + d + 4);
    float4 b0 = *(const float4*)(g_bn_b + d);
    float4 b1 = *(const float4*)(g_bn_b + d + 4);
    float y[8];
    y[0] = fmaxf(v0.x * a0.x + b0.x, 0.f);
    y[1] = fmaxf(v0.y * a0.y + b0.y, 0.f);
    y[2] = fmaxf(v0.z * a0.z + b0.z, 0.f);
    y[3] = fmaxf(v0.w * a0.w + b0.w, 0.f);
    y[4] = fmaxf(v1.x * a1.x + b1.x, 0.f);
    y[5] = fmaxf(v1.y * a1.y + b1.y, 0.f);
    y[6] = fmaxf(v1.z * a1.z + b1.z, 0.f);
    y[7] = fmaxf(v1.w * a1.w + b1.w, 0.f);
    uint32_t h[4], l[4];
#pragma unroll
    for (int q = 0; q < 4; q++) split_pair(y[2 * q], y[2 * q + 1], h[q], l[q]);
    *(uint4*)(g_xh + e) = make_uint4(h[0], h[1], h[2], h[3]);
    *(uint4*)(g_xl + e) = make_uint4(l[0], l[1], l[2], l[3]);
}

// ---------------- pooling ----------------
__global__ void pool_bounds_kernel(const int* __restrict__ batch) {
    int g = threadIdx.x;
    if (g < NG) {
        int lo = 0, hi = NN;
        while (lo < hi) {
            int mid = (lo + hi) >> 1;
            if (batch[mid] < g) lo = mid + 1; else hi = mid;
        }
        g_gstart[g] = lo;
    }
    if (g == 0) g_gstart[NG] = NN;
}

__global__ void pool_kernel() {
    int g = blockIdx.x;
    int d = threadIdx.x;
    int r0 = g_gstart[g], r1 = g_gstart[g + 1];
    float s = 0;
#pragma unroll 4
    for (int r = r0; r < r1; r++) {
        size_t off = (size_t)r * DIM + d;
        s += __bfloat162float(g_xh[off]) + __bfloat162float(g_xl[off]);
    }
    int c = r1 - r0;
    g_pool[g * DIM + d] = s / (float)(c > 0 ? c : 1);
}

// ---------------- MLP ----------------
__global__ void mlp1_kernel(const float* __restrict__ w, const float* __restrict__ bias) {
    __shared__ float xr[256];
    int g = blockIdx.x, n = threadIdx.x;
    xr[n] = g_pool[g * 256 + n];
    xr[n + 128] = g_pool[g * 256 + n + 128];
    __syncthreads();
    float s = bias[n];
#pragma unroll 8
    for (int k = 0; k < 256; k++) s += xr[k] * w[k * 128 + n];
    g_mlp1[g * 128 + n] = fmaxf(s, 0.0f);
}

__global__ void mlp2_kernel(const float* __restrict__ w, const float* __restrict__ bias) {
    __shared__ float xr[128];
    int g = blockIdx.x, n = threadIdx.x;
    xr[n] = g_mlp1[g * 128 + n];
    xr[n + 64] = g_mlp1[g * 128 + n + 64];
    __syncthreads();
    float s = bias[n];
#pragma unroll 8
    for (int k = 0; k < 128; k++) s += xr[k] * w[k * 64 + n];
    g_mlp2[g * 64 + n] = fmaxf(s, 0.0f);
}

__global__ void mlp3_kernel(const float* __restrict__ w, const float* __restrict__ bias,
                            float* __restrict__ out) {
    __shared__ float xr[64];
    int g = blockIdx.x, n = threadIdx.x;
    if (n < 32) { xr[n] = g_mlp2[g * 64 + n]; xr[n + 32] = g_mlp2[g * 64 + n + 32]; }
    __syncthreads();
    if (n >= 10) return;
    float s = bias[n];
#pragma unroll 8
    for (int k = 0; k < 64; k++) s += xr[k] * w[k * 10 + n];
    out[g * 10 + n] = s;
}

// ---------------- host launch ----------------
extern "C" void kernel_launch(void* const* d_in, const int* in_sizes, int n_in,
                              void* d_out, int out_size) {
    const float* x     = (const float*)d_in[0];
    const int*   ei    = (const int*)d_in[1];
    const int*   batch = (const int*)d_in[2];
    const float* Wl    = (const float*)d_in[3];
    const float* bl    = (const float*)d_in[4];
    const float* Wr    = (const float*)d_in[5];
    const float* gamma = (const float*)d_in[6];
    const float* beta  = (const float*)d_in[7];
    const float* fc1_w = (const float*)d_in[8];
    const float* fc1_b = (const float*)d_in[9];
    const float* fc2_w = (const float*)d_in[10];
    const float* fc2_b = (const float*)d_in[11];
    const float* fc3_w = (const float*)d_in[12];
    const float* fc3_b = (const float*)d_in[13];
    float* out = (float*)d_out;

    static bool attr_set = false;
    if (!attr_set) {
        cudaFuncSetAttribute(gemm_mma_kernel, cudaFuncAttributeMaxDynamicSharedMemorySize, GSM);
        cudaFuncSetAttribute(scan_kernel, cudaFuncAttributeMaxDynamicSharedMemorySize, NN * 4);
        attr_set = true;
    }

    // graph structure
    zero_int_kernel<<<(NN + 255) / 256, 256>>>();
    deg_kernel<<<(NE + 255) / 256, 256>>>(ei);
    scan_kernel<<<1, 512, NN * 4>>>();
    fill_kernel<<<(NE + 255) / 256, 256>>>(ei);
    sort_adj_kernel<<<(NN + 255) / 256, 256>>>();

    cvt_x_kernel<<<(NN * DIM / 8 + 255) / 256, 256>>>(x);
    wtconv_kernel<<<dim3(16, 8, NLAYER), dim3(32, 32)>>>(Wl, Wr);

    for (int i = 0; i < NLAYER; i++) {
        gather_kernel<<<(NN * 32 + 255) / 256, 256>>>();
        gemm_mma_kernel<<<dim3((NN + 127) / 128, 2), 256, GSM>>>(i, bl + (size_t)i * DIM);
        bn_reduce_kernel<<<1, DIM>>>(gamma + (size_t)i * DIM, beta + (size_t)i * DIM);
        bnapply_kernel<<<(NN * DIM / 8 + 255) / 256, 256>>>();
    }

    pool_bounds_kernel<<<1, 256>>>(batch);
    pool_kernel<<<NG, DIM>>>();
    mlp1_kernel<<<NG, 128>>>(fc1_w, fc1_b);
    mlp2_kernel<<<NG, 64>>>(fc2_w, fc2_b);
    mlp3_kernel<<<NG, 32>>>(fc3_w, fc3_b, out);
}

// round 10
// speedup vs baseline: 1.9212x; 1.1251x over previous
#include <cuda_runtime.h>
#include <cuda_bf16.h>
#include <cstdint>

#define NN 20000
#define NE 320000
#define NG 256
#define DIM 256
#define NLAYER 4
#define EPS_BN 1e-5f
#define NB_STAT 157   // ceil(20000/128) = gemm grid.x

// ---------------- device scratch (static, no allocation) ----------------
__device__ __align__(16) float g_h[(size_t)NN * DIM];
__device__ __align__(16) __nv_bfloat16 g_xh[(size_t)NN * DIM];
__device__ __align__(16) __nv_bfloat16 g_xl[(size_t)NN * DIM];
__device__ __align__(16) __nv_bfloat16 g_aggh[(size_t)NN * DIM];
__device__ __align__(16) __nv_bfloat16 g_aggl[(size_t)NN * DIM];
__device__ float g_invdeg[NN];
__device__ int   g_deg[NN];
__device__ int   g_fillpos[NN];
__device__ int   g_rowptr[NN + 1];
__device__ int   g_colidx[NE];
__device__ int   g_colidx2[NE];
__device__ float g_psum[NB_STAT * DIM];
__device__ float g_psum2[NB_STAT * DIM];
__device__ float g_bn_a[DIM];
__device__ float g_bn_b[DIM];
// transposed + bf16-split weights: [L][2(hi/lo)][256 n][512 k]
__device__ __align__(16) __nv_bfloat16 g_wt[(size_t)NLAYER * 2 * 256 * 512];

__device__ __forceinline__ uint32_t smem_u32(const void* p) {
    uint32_t a;
    asm("{ .reg .u64 t; cvta.to.shared.u64 t, %1; cvt.u32.u64 %0, t; }" : "=r"(a) : "l"(p));
    return a;
}

__device__ __forceinline__ void split_pair(float x, float y, uint32_t& h, uint32_t& l) {
    __nv_bfloat162 hb = __floats2bfloat162_rn(x, y);
    float hx = __low2float(hb), hy = __high2float(hb);
    __nv_bfloat162 lb = __floats2bfloat162_rn(x - hx, y - hy);
    h = *reinterpret_cast<uint32_t*>(&hb);
    l = *reinterpret_cast<uint32_t*>(&lb);
}

// ---------------- input conversion (+ zero of structure counters) ------------
__global__ void cvt_x_kernel(const float* __restrict__ x) {
    int t = blockIdx.x * blockDim.x + threadIdx.x;
    if (t < NN) { g_deg[t] = 0; g_fillpos[t] = 0; }
    size_t e = (size_t)t * 8;
    if (e >= (size_t)NN * DIM) return;
    float4 v0 = *(const float4*)(x + e);
    float4 v1 = *(const float4*)(x + e + 4);
    uint32_t h[4], l[4];
    split_pair(v0.x, v0.y, h[0], l[0]);
    split_pair(v0.z, v0.w, h[1], l[1]);
    split_pair(v1.x, v1.y, h[2], l[2]);
    split_pair(v1.z, v1.w, h[3], l[3]);
    *(uint4*)(g_xh + e) = make_uint4(h[0], h[1], h[2], h[3]);
    *(uint4*)(g_xl + e) = make_uint4(l[0], l[1], l[2], l[3]);
}

// ---------------- graph structure build ----------------
__global__ void deg_kernel(const int* __restrict__ ei) {
    int e = blockIdx.x * blockDim.x + threadIdx.x;
    if (e >= NE) return;
    atomicAdd(&g_deg[ei[NE + e]], 1);
}

// single-block scan (smem-staged), also emits invdeg. 1024 threads.
__global__ void scan_kernel() {
    extern __shared__ int sdeg[];
    __shared__ int wsum[32];
    int tid = threadIdx.x;
    for (int i = tid; i < NN; i += 1024) {
        int d = g_deg[i];
        sdeg[i] = d;
        g_invdeg[i] = (d > 0) ? 1.0f / (float)d : 0.0f;
    }
    __syncthreads();
    const int PER = 20;  // 1024*20 = 20480 >= NN
    int i0 = tid * PER;
    int s = 0;
#pragma unroll 4
    for (int j = 0; j < PER; j++) {
        int i = i0 + j;
        if (i < NN) s += sdeg[i];
    }
    int lane = tid & 31, warp = tid >> 5;
    int inc = s;
    for (int off = 1; off < 32; off <<= 1) {
        int t = __shfl_up_sync(0xFFFFFFFFu, inc, off);
        if (lane >= off) inc += t;
    }
    if (lane == 31) wsum[warp] = inc;
    __syncthreads();
    if (warp == 0) {
        int v = wsum[lane];
        for (int off = 1; off < 32; off <<= 1) {
            int t = __shfl_up_sync(0xFFFFFFFFu, v, off);
            if (lane >= off) v += t;
        }
        wsum[lane] = v;
    }
    __syncthreads();
    int prefix = inc - s + (warp > 0 ? wsum[warp - 1] : 0);  // exclusive
    int run = prefix;
    for (int j = 0; j < PER; j++) {
        int i = i0 + j;
        if (i < NN) { int d = sdeg[i]; sdeg[i] = run; run += d; }
    }
    if (tid == 1023) g_rowptr[NN] = run;
    __syncthreads();
    for (int i = tid; i < NN; i += 1024) g_rowptr[i] = sdeg[i];
}

__global__ void fill_kernel(const int* __restrict__ ei) {
    int e = blockIdx.x * blockDim.x + threadIdx.x;
    if (e >= NE) return;
    int src = ei[e];
    int dst = ei[NE + e];
    int p = atomicAdd(&g_fillpos[dst], 1);
    g_colidx[g_rowptr[dst] + p] = src;
}

// warp-parallel stable rank sort per adjacency list (deterministic sum order)
__global__ void reorder_kernel() {
    int warp = (blockIdx.x * blockDim.x + threadIdx.x) >> 5;
    int lane = threadIdx.x & 31;
    if (warp >= NN) return;
    int b = g_rowptr[warp], e = g_rowptr[warp + 1];
    int d = e - b;
    for (int i = lane; i < d; i += 32) {
        int key = g_colidx[b + i];
        int rank = 0;
        for (int j = 0; j < d; j++) {
            int kj = g_colidx[b + j];
            rank += (kj < key) || (kj == key && j < i);
        }
        g_colidx2[b + rank] = key;
    }
}

// ---------------- weight transpose + bf16 split ----------------
__global__ void wtconv_kernel(const float* __restrict__ Wl, const float* __restrict__ Wr) {
    __shared__ float t[32][33];
    int L = blockIdx.z, k0 = blockIdx.x * 32, n0 = blockIdx.y * 32;
    int tx = threadIdx.x, ty = threadIdx.y;
    const float* W = (k0 < 256) ? (Wl + (size_t)L * 65536 + (size_t)k0 * 256)
                                : (Wr + (size_t)L * 65536 + (size_t)(k0 - 256) * 256);
    t[ty][tx] = W[(size_t)ty * 256 + n0 + tx];
    __syncthreads();
    float v = t[tx][ty];  // = W[k0+tx][n0+ty]
    int n = n0 + ty, k = k0 + tx;
    __nv_bfloat16 hb = __float2bfloat16(v);
    __nv_bfloat16 lb = __float2bfloat16(v - __bfloat162float(hb));
    size_t base = (size_t)L * 262144;
    g_wt[base + (size_t)n * 512 + k] = hb;
    g_wt[base + 131072 + (size_t)n * 512 + k] = lb;
}

// ---------------- mean aggregation: warp per node, bf16-pair in/out ----------
__global__ void gather_kernel() {
    int warp = (blockIdx.x * blockDim.x + threadIdx.x) >> 5;
    int lane = threadIdx.x & 31;
    if (warp >= NN) return;
    int b = g_rowptr[warp], e = g_rowptr[warp + 1];
    int col = lane * 8;
    float a[8] = {0, 0, 0, 0, 0, 0, 0, 0};
    for (int j = b; j < e; j++) {
        int u = g_colidx2[j];
        size_t off = (size_t)u * DIM + col;
        uint4 hq = *(const uint4*)(g_xh + off);
        uint4 lq = *(const uint4*)(g_xl + off);
        const __nv_bfloat162* hp = (const __nv_bfloat162*)&hq;
        const __nv_bfloat162* lp = (const __nv_bfloat162*)&lq;
#pragma unroll
        for (int q = 0; q < 4; q++) {
            float2 hf = __bfloat1622float2(hp[q]);
            float2 lf = __bfloat1622float2(lp[q]);
            a[2 * q] += hf.x + lf.x;
            a[2 * q + 1] += hf.y + lf.y;
        }
    }
    float s = g_invdeg[warp];
    uint32_t h[4], l[4];
#pragma unroll
    for (int q = 0; q < 4; q++) split_pair(a[2 * q] * s, a[2 * q + 1] * s, h[q], l[q]);
    size_t off = (size_t)warp * DIM + col;
    *(uint4*)(g_aggh + off) = make_uint4(h[0], h[1], h[2], h[3]);
    *(uint4*)(g_aggl + off) = make_uint4(l[0], l[1], l[2], l[3]);
}

// ---------------- pipelined mma.sync GEMM + fused BN stats -------------------
#define AHI 0
#define ALO 10240
#define BHI 20480
#define BLO 30720
#define STAGE 40960
#define GSM (2 * STAGE)

#define CPA(dst, src, sz) \
    asm volatile("cp.async.cg.shared.global [%0], [%1], 16, %2;" \
        :: "r"(dst), "l"(src), "r"(sz) : "memory")
#define CPC() asm volatile("cp.async.commit_group;" ::: "memory")
#define CPW(n) asm volatile("cp.async.wait_group %0;" :: "n"(n) : "memory")

#define LDSM4(r, addr) \
    asm volatile("ldmatrix.sync.aligned.m8n8.x4.shared.b16 {%0,%1,%2,%3}, [%4];" \
        : "=r"((r)[0]), "=r"((r)[1]), "=r"((r)[2]), "=r"((r)[3]) : "r"(addr))

#define MMA16816(c, a, b0_, b1_) \
    asm volatile("mma.sync.aligned.m16n8k16.row.col.f32.bf16.bf16.f32 " \
        "{%0,%1,%2,%3}, {%4,%5,%6,%7}, {%8,%9}, {%0,%1,%2,%3};" \
        : "+f"((c)[0]), "+f"((c)[1]), "+f"((c)[2]), "+f"((c)[3]) \
        : "r"((a)[0]), "r"((a)[1]), "r"((a)[2]), "r"((a)[3]), "r"(b0_), "r"(b1_))

__device__ __forceinline__ void load_stage(int s, uint32_t sb, int m0,
                                           const __nv_bfloat16* wtL) {
    const __nv_bfloat16* Ah = (s < 8) ? g_aggh : g_xh;
    const __nv_bfloat16* Al = (s < 8) ? g_aggl : g_xl;
    int kg = (s & 7) * 32;
    int tid = threadIdx.x;
#pragma unroll
    for (int i = 0; i < 2; i++) {
        int idx = tid + i * 256;
        int row = idx >> 2, q = idx & 3;
        int gm = m0 + row;
        uint32_t sz = (gm < NN) ? 16u : 0u;
        int gmc = (gm < NN) ? gm : 0;
        size_t so = (size_t)gmc * 256 + kg + q * 8;
        uint32_t off = (uint32_t)row * 80 + q * 16;
        CPA(sb + AHI + off, Ah + so, sz);
        CPA(sb + ALO + off, Al + so, sz);
    }
#pragma unroll
    for (int i = 0; i < 2; i++) {
        int idx = tid + i * 256;
        int row = idx >> 2, q = idx & 3;
        const __nv_bfloat16* src = wtL + (size_t)row * 512 + s * 32 + q * 8;
        uint32_t off = (uint32_t)row * 80 + q * 16;
        CPA(sb + BHI + off, src, 16u);
        CPA(sb + BLO + off, src + 131072, 16u);
    }
}

__global__ void __launch_bounds__(256, 2)
gemm_mma_kernel(int layer, const float* __restrict__ bl_) {
    extern __shared__ char sm[];
    __shared__ float sred[2][128][2];  // [wm][local col][{sum, sumsq}]
    uint32_t sb = smem_u32(sm);
    int tid = threadIdx.x;
    int lane = tid & 31, wid = tid >> 5;
    int wm = wid >> 2, wn = wid & 3;           // warp tile: 64(M) x 32(N)
    int m0 = blockIdx.x * 128, n0 = blockIdx.y * 128;
    const __nv_bfloat16* wtL = g_wt + (size_t)layer * 262144 + (size_t)n0 * 512;

    float C[4][4][4];
#pragma unroll
    for (int i = 0; i < 4; i++)
#pragma unroll
        for (int j = 0; j < 4; j++)
#pragma unroll
            for (int q = 0; q < 4; q++) C[i][j][q] = 0.0f;

    uint32_t a_row = (uint32_t)(wm * 64 + (lane & 15));
    uint32_t a_koff = (uint32_t)((lane >> 4) * 8);
    uint32_t b_row = (uint32_t)(wn * 32 + ((lane >> 4) & 1) * 8 + (lane & 7));
    uint32_t b_koff = (uint32_t)(((lane >> 3) & 1) * 8);

    load_stage(0, sb, m0, wtL);
    CPC();

    for (int s = 0; s < 16; s++) {
        if (s < 15) {
            load_stage(s + 1, sb + ((uint32_t)(s + 1) & 1u) * STAGE, m0, wtL);
            CPC();
            CPW(1);
        } else {
            CPW(0);
        }
        __syncthreads();
        uint32_t bufb = sb + ((uint32_t)s & 1u) * STAGE;
#pragma unroll
        for (int kl = 0; kl < 32; kl += 16) {
            uint32_t bh[2][4], blo_[2][4];
#pragma unroll
            for (int nf16 = 0; nf16 < 2; nf16++) {
                uint32_t ro = (b_row + nf16 * 16) * 80 + (b_koff + kl) * 2;
                LDSM4(bh[nf16], bufb + BHI + ro);
                LDSM4(blo_[nf16], bufb + BLO + ro);
            }
#pragma unroll
            for (int mf = 0; mf < 4; mf++) {
                uint32_t ah[4], al[4];
                uint32_t ro = (a_row + mf * 16) * 80 + (a_koff + kl) * 2;
                LDSM4(ah, bufb + AHI + ro);
                LDSM4(al, bufb + ALO + ro);
#pragma unroll
                for (int nf = 0; nf < 4; nf++) {
                    uint32_t b0 = bh[nf >> 1][(nf & 1) * 2];
                    uint32_t b1 = bh[nf >> 1][(nf & 1) * 2 + 1];
                    uint32_t lb0 = blo_[nf >> 1][(nf & 1) * 2];
                    uint32_t lb1 = blo_[nf >> 1][(nf & 1) * 2 + 1];
                    MMA16816(C[mf][nf], ah, b0, b1);
                    MMA16816(C[mf][nf], al, b0, b1);
                    MMA16816(C[mf][nf], ah, lb0, lb1);
                }
            }
        }
        __syncthreads();
    }
    // ---- epilogue: bias + store + fused BN stats ----
    int mbase = m0 + wm * 64;
    int nbase = n0 + wn * 32;
    float ts[4][2], ts2[4][2];
#pragma unroll
    for (int nf = 0; nf < 4; nf++) {
        ts[nf][0] = ts[nf][1] = 0.f;
        ts2[nf][0] = ts2[nf][1] = 0.f;
    }
#pragma unroll
    for (int mf = 0; mf < 4; mf++) {
#pragma unroll
        for (int nf = 0; nf < 4; nf++) {
            int c = nbase + nf * 8 + (lane & 3) * 2;
            float bv0 = bl_[c], bv1 = bl_[c + 1];
            int r0 = mbase + mf * 16 + (lane >> 2);
            if (r0 < NN) {
                float ox = C[mf][nf][0] + bv0, oy = C[mf][nf][1] + bv1;
                *(float2*)(g_h + (size_t)r0 * 256 + c) = make_float2(ox, oy);
                ts[nf][0] += ox; ts2[nf][0] += ox * ox;
                ts[nf][1] += oy; ts2[nf][1] += oy * oy;
            }
            int r1 = r0 + 8;
            if (r1 < NN) {
                float ox = C[mf][nf][2] + bv0, oy = C[mf][nf][3] + bv1;
                *(float2*)(g_h + (size_t)r1 * 256 + c) = make_float2(ox, oy);
                ts[nf][0] += ox; ts2[nf][0] += ox * ox;
                ts[nf][1] += oy; ts2[nf][1] += oy * oy;
            }
        }
    }
#pragma unroll
    for (int nf = 0; nf < 4; nf++) {
#pragma unroll
        for (int i = 0; i < 2; i++) {
#pragma unroll
            for (int msk = 4; msk < 32; msk <<= 1) {
                ts[nf][i] += __shfl_xor_sync(0xFFFFFFFFu, ts[nf][i], msk);
                ts2[nf][i] += __shfl_xor_sync(0xFFFFFFFFu, ts2[nf][i], msk);
            }
        }
    }
    if (lane < 4) {
#pragma unroll
        for (int nf = 0; nf < 4; nf++) {
            int coll = wn * 32 + nf * 8 + lane * 2;
            sred[wm][coll][0] = ts[nf][0];
            sred[wm][coll][1] = ts2[nf][0];
            sred[wm][coll + 1][0] = ts[nf][1];
            sred[wm][coll + 1][1] = ts2[nf][1];
        }
    }
    __syncthreads();
    if (tid < 128) {
        float s = sred[0][tid][0] + sred[1][tid][0];
        float s2 = sred[0][tid][1] + sred[1][tid][1];
        int cg = blockIdx.x * 256 + n0 + tid;
        g_psum[cg] = s;
        g_psum2[cg] = s2;
    }
}

// ---------------- BatchNorm reduce (tiny) ----------------
__global__ void bn_reduce_kernel(const float* __restrict__ gamma, const float* __restrict__ beta) {
    int d = threadIdx.x;
    float s = 0, s2 = 0;
    for (int b = 0; b < NB_STAT; b++) {
        s += g_psum[b * DIM + d];
        s2 += g_psum2[b * DIM + d];
    }
    float mu = s / (float)NN;
    float var = s2 / (float)NN - mu * mu;
    float r = rsqrtf(var + EPS_BN);
    float a = gamma[d] * r;
    g_bn_a[d] = a;
    g_bn_b[d] = beta[d] - mu * a;
}

// relu(bn(h)) -> bf16 hi/lo split
__global__ void bnapply_kernel() {
    size_t e = (size_t)(blockIdx.x * blockDim.x + threadIdx.x) * 8;
    if (e >= (size_t)NN * DIM) return;
    int d = (int)(e & 255u);
    float4 v0 = *(const float4*)(g_h + e);
    float4 v1 = *(const float4*)(g_h + e + 4);
    float4 a0 = *(const float4*)(g_bn_a + d);
    float4 a1 = *(const float4*)(g_bn_a + d + 4);
    float4 b0 = *(const float4*)(g_bn_b + d);
    float4 b1 = *(const float4*)(g_bn_b + d + 4);
    float y[8];
    y[0] = fmaxf(v0.x * a0.x + b0.x, 0.f);
    y[1] = fmaxf(v0.y * a0.y + b0.y, 0.f);
    y[2] = fmaxf(v0.z * a0.z + b0.z, 0.f);
    y[3] = fmaxf(v0.w * a0.w + b0.w, 0.f);
    y[4] = fmaxf(v1.x * a1.x + b1.x, 0.f);
    y[5] = fmaxf(v1.y * a1.y + b1.y, 0.f);
    y[6] = fmaxf(v1.z * a1.z + b1.z, 0.f);
    y[7] = fmaxf(v1.w * a1.w + b1.w, 0.f);
    uint32_t h[4], l[4];
#pragma unroll
    for (int q = 0; q < 4; q++) split_pair(y[2 * q], y[2 * q + 1], h[q], l[q]);
    *(uint4*)(g_xh + e) = make_uint4(h[0], h[1], h[2], h[3]);
    *(uint4*)(g_xl + e) = make_uint4(l[0], l[1], l[2], l[3]);
}

// ---------------- fused tail: pool + 3-layer MLP, one block per graph --------
__device__ __forceinline__ int lower_bound_batch(const int* __restrict__ batch, int g) {
    int lo = 0, hi = NN;
    while (lo < hi) {
        int mid = (lo + hi) >> 1;
        if (batch[mid] < g) lo = mid + 1; else hi = mid;
    }
    return lo;
}

__global__ void tail_kernel(const int* __restrict__ batch,
                            const float* __restrict__ fc1_w, const float* __restrict__ fc1_b,
                            const float* __restrict__ fc2_w, const float* __restrict__ fc2_b,
                            const float* __restrict__ fc3_w, const float* __restrict__ fc3_b,
                            float* __restrict__ out) {
    __shared__ float xr[256];
    __shared__ float y1[128];
    __shared__ float y2[64];
    int g = blockIdx.x;
    int n = threadIdx.x;  // 256 threads
    int r0 = lower_bound_batch(batch, g);
    int r1 = lower_bound_batch(batch, g + 1);
    float s = 0;
#pragma unroll 4
    for (int r = r0; r < r1; r++) {
        size_t off = (size_t)r * DIM + n;
        s += __bfloat162float(g_xh[off]) + __bfloat162float(g_xl[off]);
    }
    int c = r1 - r0;
    xr[n] = s / (float)(c > 0 ? c : 1);
    __syncthreads();
    if (n < 128) {
        float t = fc1_b[n];
#pragma unroll 8
        for (int k = 0; k < 256; k++) t += xr[k] * fc1_w[k * 128 + n];
        y1[n] = fmaxf(t, 0.0f);
    }
    __syncthreads();
    if (n < 64) {
        float t = fc2_b[n];
#pragma unroll 8
        for (int k = 0; k < 128; k++) t += y1[k] * fc2_w[k * 64 + n];
        y2[n] = fmaxf(t, 0.0f);
    }
    __syncthreads();
    if (n < 10) {
        float t = fc3_b[n];
#pragma unroll 8
        for (int k = 0; k < 64; k++) t += y2[k] * fc3_w[k * 10 + n];
        out[g * 10 + n] = t;
    }
}

// ---------------- host launch ----------------
extern "C" void kernel_launch(void* const* d_in, const int* in_sizes, int n_in,
                              void* d_out, int out_size) {
    const float* x     = (const float*)d_in[0];
    const int*   ei    = (const int*)d_in[1];
    const int*   batch = (const int*)d_in[2];
    const float* Wl    = (const float*)d_in[3];
    const float* bl    = (const float*)d_in[4];
    const float* Wr    = (const float*)d_in[5];
    const float* gamma = (const float*)d_in[6];
    const float* beta  = (const float*)d_in[7];
    const float* fc1_w = (const float*)d_in[8];
    const float* fc1_b = (const float*)d_in[9];
    const float* fc2_w = (const float*)d_in[10];
    const float* fc2_b = (const float*)d_in[11];
    const float* fc3_w = (const float*)d_in[12];
    const float* fc3_b = (const float*)d_in[13];
    float* out = (float*)d_out;

    static bool attr_set = false;
    if (!attr_set) {
        cudaFuncSetAttribute(gemm_mma_kernel, cudaFuncAttributeMaxDynamicSharedMemorySize, GSM);
        cudaFuncSetAttribute(scan_kernel, cudaFuncAttributeMaxDynamicSharedMemorySize, NN * 4);
        attr_set = true;
    }

    // structure + conversions
    cvt_x_kernel<<<(NN * DIM / 8 + 255) / 256, 256>>>(x);   // also zeroes deg/fillpos
    deg_kernel<<<(NE + 255) / 256, 256>>>(ei);
    scan_kernel<<<1, 1024, NN * 4>>>();
    fill_kernel<<<(NE + 255) / 256, 256>>>(ei);
    reorder_kernel<<<(NN * 32 + 255) / 256, 256>>>();
    wtconv_kernel<<<dim3(16, 8, NLAYER), dim3(32, 32)>>>(Wl, Wr);

    for (int i = 0; i < NLAYER; i++) {
        gather_kernel<<<(NN * 32 + 255) / 256, 256>>>();
        gemm_mma_kernel<<<dim3((NN + 127) / 128, 2), 256, GSM>>>(i, bl + (size_t)i * DIM);
        bn_reduce_kernel<<<1, DIM>>>(gamma + (size_t)i * DIM, beta + (size_t)i * DIM);
        bnapply_kernel<<<(NN * DIM / 8 + 255) / 256, 256>>>();
    }

    tail_kernel<<<NG, 256>>>(batch, fc1_w, fc1_b, fc2_w, fc2_b, fc3_w, fc3_b, out);
}

// round 11
// speedup vs baseline: 2.1070x; 1.0968x over previous
#include <cuda_runtime.h>
#include <cuda_bf16.h>
#include <cstdint>

#define NN 20000
#define NE 320000
#define NG 256
#define DIM 256
#define NLAYER 4
#define EPS_BN 1e-5f
#define MTILE 160
#define NB_STAT 125   // 20000/160 = gemm grid.x (exact)

// ---------------- device scratch (static, no allocation) ----------------
__device__ __align__(16) float g_h[(size_t)NN * DIM];
__device__ __align__(16) __nv_bfloat16 g_xh[(size_t)NN * DIM];
__device__ __align__(16) __nv_bfloat16 g_xl[(size_t)NN * DIM];
__device__ __align__(16) __nv_bfloat16 g_aggh[(size_t)NN * DIM];
__device__ __align__(16) __nv_bfloat16 g_aggl[(size_t)NN * DIM];
__device__ float g_invdeg[NN];
__device__ int   g_deg[NN];
__device__ int   g_fillpos[NN];
__device__ int   g_rowptr[NN + 1];
__device__ int   g_colidx[NE];
__device__ int   g_colidx2[NE];
__device__ float g_psum[NB_STAT * DIM];
__device__ float g_psum2[NB_STAT * DIM];
__device__ float g_bn_a[DIM];
__device__ float g_bn_b[DIM];
// transposed + bf16-split weights: [L][2(hi/lo)][256 n][512 k]
__device__ __align__(16) __nv_bfloat16 g_wt[(size_t)NLAYER * 2 * 256 * 512];

__device__ __forceinline__ uint32_t smem_u32(const void* p) {
    uint32_t a;
    asm("{ .reg .u64 t; cvta.to.shared.u64 t, %1; cvt.u32.u64 %0, t; }" : "=r"(a) : "l"(p));
    return a;
}

__device__ __forceinline__ void split_pair(float x, float y, uint32_t& h, uint32_t& l) {
    __nv_bfloat162 hb = __floats2bfloat162_rn(x, y);
    float hx = __low2float(hb), hy = __high2float(hb);
    __nv_bfloat162 lb = __floats2bfloat162_rn(x - hx, y - hy);
    h = *reinterpret_cast<uint32_t*>(&hb);
    l = *reinterpret_cast<uint32_t*>(&lb);
}

// ---------------- input conversion (+ zero of structure counters) ------------
__global__ void cvt_x_kernel(const float* __restrict__ x) {
    int t = blockIdx.x * blockDim.x + threadIdx.x;
    if (t < NN) { g_deg[t] = 0; g_fillpos[t] = 0; }
    size_t e = (size_t)t * 8;
    if (e >= (size_t)NN * DIM) return;
    float4 v0 = *(const float4*)(x + e);
    float4 v1 = *(const float4*)(x + e + 4);
    uint32_t h[4], l[4];
    split_pair(v0.x, v0.y, h[0], l[0]);
    split_pair(v0.z, v0.w, h[1], l[1]);
    split_pair(v1.x, v1.y, h[2], l[2]);
    split_pair(v1.z, v1.w, h[3], l[3]);
    *(uint4*)(g_xh + e) = make_uint4(h[0], h[1], h[2], h[3]);
    *(uint4*)(g_xl + e) = make_uint4(l[0], l[1], l[2], l[3]);
}

// ---------------- graph structure build ----------------
__global__ void deg_kernel(const int* __restrict__ ei) {
    int e = blockIdx.x * blockDim.x + threadIdx.x;
    if (e >= NE) return;
    atomicAdd(&g_deg[ei[NE + e]], 1);
}

// single-block scan (smem-staged), also emits invdeg. 1024 threads.
__global__ void scan_kernel() {
    extern __shared__ int sdeg[];
    __shared__ int wsum[32];
    int tid = threadIdx.x;
    for (int i = tid; i < NN; i += 1024) {
        int d = g_deg[i];
        sdeg[i] = d;
        g_invdeg[i] = (d > 0) ? 1.0f / (float)d : 0.0f;
    }
    __syncthreads();
    const int PER = 20;  // 1024*20 = 20480 >= NN
    int i0 = tid * PER;
    int s = 0;
#pragma unroll 4
    for (int j = 0; j < PER; j++) {
        int i = i0 + j;
        if (i < NN) s += sdeg[i];
    }
    int lane = tid & 31, warp = tid >> 5;
    int inc = s;
    for (int off = 1; off < 32; off <<= 1) {
        int t = __shfl_up_sync(0xFFFFFFFFu, inc, off);
        if (lane >= off) inc += t;
    }
    if (lane == 31) wsum[warp] = inc;
    __syncthreads();
    if (warp == 0) {
        int v = wsum[lane];
        for (int off = 1; off < 32; off <<= 1) {
            int t = __shfl_up_sync(0xFFFFFFFFu, v, off);
            if (lane >= off) v += t;
        }
        wsum[lane] = v;
    }
    __syncthreads();
    int prefix = inc - s + (warp > 0 ? wsum[warp - 1] : 0);  // exclusive
    int run = prefix;
    for (int j = 0; j < PER; j++) {
        int i = i0 + j;
        if (i < NN) { int d = sdeg[i]; sdeg[i] = run; run += d; }
    }
    if (tid == 1023) g_rowptr[NN] = run;
    __syncthreads();
    for (int i = tid; i < NN; i += 1024) g_rowptr[i] = sdeg[i];
}

__global__ void fill_kernel(const int* __restrict__ ei) {
    int e = blockIdx.x * blockDim.x + threadIdx.x;
    if (e >= NE) return;
    int src = ei[e];
    int dst = ei[NE + e];
    int p = atomicAdd(&g_fillpos[dst], 1);
    g_colidx[g_rowptr[dst] + p] = src;
}

// warp-parallel stable rank sort per adjacency list (deterministic sum order)
__global__ void reorder_kernel() {
    int warp = (blockIdx.x * blockDim.x + threadIdx.x) >> 5;
    int lane = threadIdx.x & 31;
    if (warp >= NN) return;
    int b = g_rowptr[warp], e = g_rowptr[warp + 1];
    int d = e - b;
    for (int i = lane; i < d; i += 32) {
        int key = g_colidx[b + i];
        int rank = 0;
        for (int j = 0; j < d; j++) {
            int kj = g_colidx[b + j];
            rank += (kj < key) || (kj == key && j < i);
        }
        g_colidx2[b + rank] = key;
    }
}

// ---------------- weight transpose + bf16 split ----------------
__global__ void wtconv_kernel(const float* __restrict__ Wl, const float* __restrict__ Wr) {
    __shared__ float t[32][33];
    int L = blockIdx.z, k0 = blockIdx.x * 32, n0 = blockIdx.y * 32;
    int tx = threadIdx.x, ty = threadIdx.y;
    const float* W = (k0 < 256) ? (Wl + (size_t)L * 65536 + (size_t)k0 * 256)
                                : (Wr + (size_t)L * 65536 + (size_t)(k0 - 256) * 256);
    t[ty][tx] = W[(size_t)ty * 256 + n0 + tx];
    __syncthreads();
    float v = t[tx][ty];  // = W[k0+tx][n0+ty]
    int n = n0 + ty, k = k0 + tx;
    __nv_bfloat16 hb = __float2bfloat16(v);
    __nv_bfloat16 lb = __float2bfloat16(v - __bfloat162float(hb));
    size_t base = (size_t)L * 262144;
    g_wt[base + (size_t)n * 512 + k] = hb;
    g_wt[base + 131072 + (size_t)n * 512 + k] = lb;
}

// ---------------- mean aggregation: warp per node, bf16-pair in/out ----------
__global__ void gather_kernel() {
    int warp = (blockIdx.x * blockDim.x + threadIdx.x) >> 5;
    int lane = threadIdx.x & 31;
    if (warp >= NN) return;
    int b = g_rowptr[warp], e = g_rowptr[warp + 1];
    int col = lane * 8;
    float a[8] = {0, 0, 0, 0, 0, 0, 0, 0};
    for (int j = b; j < e; j++) {
        int u = g_colidx2[j];
        size_t off = (size_t)u * DIM + col;
        uint4 hq = *(const uint4*)(g_xh + off);
        uint4 lq = *(const uint4*)(g_xl + off);
        const __nv_bfloat162* hp = (const __nv_bfloat162*)&hq;
        const __nv_bfloat162* lp = (const __nv_bfloat162*)&lq;
#pragma unroll
        for (int q = 0; q < 4; q++) {
            float2 hf = __bfloat1622float2(hp[q]);
            float2 lf = __bfloat1622float2(lp[q]);
            a[2 * q] += hf.x + lf.x;
            a[2 * q + 1] += hf.y + lf.y;
        }
    }
    float s = g_invdeg[warp];
    uint32_t h[4], l[4];
#pragma unroll
    for (int q = 0; q < 4; q++) split_pair(a[2 * q] * s, a[2 * q + 1] * s, h[q], l[q]);
    size_t off = (size_t)warp * DIM + col;
    *(uint4*)(g_aggh + off) = make_uint4(h[0], h[1], h[2], h[3]);
    *(uint4*)(g_aggl + off) = make_uint4(l[0], l[1], l[2], l[3]);
}

// ---------------- pipelined mma.sync GEMM + fused BN stats -------------------
// block 160(M) x 128(N), 8 warps each 80x32, K=512 in 16 stages of 32.
// per stage (46080 B): Ahi@0 (160x32 bf16, row stride 80B), Alo@12800,
// Bhi@25600, Blo@35840. Two stages double-buffered via cp.async.
#define AHI 0
#define ALO 12800
#define BHI 25600
#define BLO 35840
#define STAGE 46080
#define GSM (2 * STAGE)

#define CPA(dst, src, sz) \
    asm volatile("cp.async.cg.shared.global [%0], [%1], 16, %2;" \
        :: "r"(dst), "l"(src), "r"(sz) : "memory")
#define CPC() asm volatile("cp.async.commit_group;" ::: "memory")
#define CPW(n) asm volatile("cp.async.wait_group %0;" :: "n"(n) : "memory")

#define LDSM4(r, addr) \
    asm volatile("ldmatrix.sync.aligned.m8n8.x4.shared.b16 {%0,%1,%2,%3}, [%4];" \
        : "=r"((r)[0]), "=r"((r)[1]), "=r"((r)[2]), "=r"((r)[3]) : "r"(addr))

#define MMA16816(c, a, b0_, b1_) \
    asm volatile("mma.sync.aligned.m16n8k16.row.col.f32.bf16.bf16.f32 " \
        "{%0,%1,%2,%3}, {%4,%5,%6,%7}, {%8,%9}, {%0,%1,%2,%3};" \
        : "+f"((c)[0]), "+f"((c)[1]), "+f"((c)[2]), "+f"((c)[3]) \
        : "r"((a)[0]), "r"((a)[1]), "r"((a)[2]), "r"((a)[3]), "r"(b0_), "r"(b1_))

__device__ __forceinline__ void load_stage(int s, uint32_t sb, int m0,
                                           const __nv_bfloat16* wtL) {
    const __nv_bfloat16* Ah = (s < 8) ? g_aggh : g_xh;
    const __nv_bfloat16* Al = (s < 8) ? g_aggl : g_xl;
    int kg = (s & 7) * 32;
    int tid = threadIdx.x;
    // A: 160 rows x 4 quads = 640 items (rows always < NN: 125*160 = 20000)
#pragma unroll
    for (int i = 0; i < 3; i++) {
        int idx = tid + i * 256;
        if (idx < 640) {
            int row = idx >> 2, q = idx & 3;
            size_t so = (size_t)(m0 + row) * 256 + kg + q * 8;
            uint32_t off = (uint32_t)row * 80 + q * 16;
            CPA(sb + AHI + off, Ah + so, 16u);
            CPA(sb + ALO + off, Al + so, 16u);
        }
    }
    // B: 128 rows x 4 quads, hi+lo
#pragma unroll
    for (int i = 0; i < 2; i++) {
        int idx = tid + i * 256;
        int row = idx >> 2, q = idx & 3;
        const __nv_bfloat16* src = wtL + (size_t)row * 512 + s * 32 + q * 8;
        uint32_t off = (uint32_t)row * 80 + q * 16;
        CPA(sb + BHI + off, src, 16u);
        CPA(sb + BLO + off, src + 131072, 16u);
    }
}

__global__ void __launch_bounds__(256, 2)
gemm_mma_kernel(int layer, const float* __restrict__ bl_) {
    extern __shared__ char sm[];
    __shared__ float sred[2][128][2];  // [wm][local col][{sum, sumsq}]
    uint32_t sb = smem_u32(sm);
    int tid = threadIdx.x;
    int lane = tid & 31, wid = tid >> 5;
    int wm = wid >> 2, wn = wid & 3;           // warp tile: 80(M) x 32(N)
    int m0 = blockIdx.x * MTILE, n0 = blockIdx.y * 128;
    const __nv_bfloat16* wtL = g_wt + (size_t)layer * 262144 + (size_t)n0 * 512;

    float C[5][4][4];
#pragma unroll
    for (int i = 0; i < 5; i++)
#pragma unroll
        for (int j = 0; j < 4; j++)
#pragma unroll
            for (int q = 0; q < 4; q++) C[i][j][q] = 0.0f;

    uint32_t a_row = (uint32_t)(wm * 80 + (lane & 15));
    uint32_t a_koff = (uint32_t)((lane >> 4) * 8);
    uint32_t b_row = (uint32_t)(wn * 32 + ((lane >> 4) & 1) * 8 + (lane & 7));
    uint32_t b_koff = (uint32_t)(((lane >> 3) & 1) * 8);

    load_stage(0, sb, m0, wtL);
    CPC();

    for (int s = 0; s < 16; s++) {
        if (s < 15) {
            load_stage(s + 1, sb + ((uint32_t)(s + 1) & 1u) * STAGE, m0, wtL);
            CPC();
            CPW(1);
        } else {
            CPW(0);
        }
        __syncthreads();
        uint32_t bufb = sb + ((uint32_t)s & 1u) * STAGE;
#pragma unroll
        for (int kl = 0; kl < 32; kl += 16) {
            uint32_t bh[2][4], blo_[2][4];
#pragma unroll
            for (int nf16 = 0; nf16 < 2; nf16++) {
                uint32_t ro = (b_row + nf16 * 16) * 80 + (b_koff + kl) * 2;
                LDSM4(bh[nf16], bufb + BHI + ro);
                LDSM4(blo_[nf16], bufb + BLO + ro);
            }
#pragma unroll
            for (int mf = 0; mf < 5; mf++) {
                uint32_t ah[4], al[4];
                uint32_t ro = (a_row + mf * 16) * 80 + (a_koff + kl) * 2;
                LDSM4(ah, bufb + AHI + ro);
                LDSM4(al, bufb + ALO + ro);
#pragma unroll
                for (int nf = 0; nf < 4; nf++) {
                    uint32_t b0 = bh[nf >> 1][(nf & 1) * 2];
                    uint32_t b1 = bh[nf >> 1][(nf & 1) * 2 + 1];
                    uint32_t lb0 = blo_[nf >> 1][(nf & 1) * 2];
                    uint32_t lb1 = blo_[nf >> 1][(nf & 1) * 2 + 1];
                    MMA16816(C[mf][nf], ah, b0, b1);
                    MMA16816(C[mf][nf], al, b0, b1);
                    MMA16816(C[mf][nf], ah, lb0, lb1);
                }
            }
        }
        __syncthreads();
    }
    // ---- epilogue: bias + store + fused BN stats (rows always in-range) ----
    int mbase = m0 + wm * 80;
    int nbase = n0 + wn * 32;
    float ts[4][2], ts2[4][2];
#pragma unroll
    for (int nf = 0; nf < 4; nf++) {
        ts[nf][0] = ts[nf][1] = 0.f;
        ts2[nf][0] = ts2[nf][1] = 0.f;
    }
#pragma unroll
    for (int mf = 0; mf < 5; mf++) {
#pragma unroll
        for (int nf = 0; nf < 4; nf++) {
            int c = nbase + nf * 8 + (lane & 3) * 2;
            float bv0 = bl_[c], bv1 = bl_[c + 1];
            int r0 = mbase + mf * 16 + (lane >> 2);
            {
                float ox = C[mf][nf][0] + bv0, oy = C[mf][nf][1] + bv1;
                *(float2*)(g_h + (size_t)r0 * 256 + c) = make_float2(ox, oy);
                ts[nf][0] += ox; ts2[nf][0] += ox * ox;
                ts[nf][1] += oy; ts2[nf][1] += oy * oy;
            }
            {
                int r1 = r0 + 8;
                float ox = C[mf][nf][2] + bv0, oy = C[mf][nf][3] + bv1;
                *(float2*)(g_h + (size_t)r1 * 256 + c) = make_float2(ox, oy);
                ts[nf][0] += ox; ts2[nf][0] += ox * ox;
                ts[nf][1] += oy; ts2[nf][1] += oy * oy;
            }
        }
    }
#pragma unroll
    for (int nf = 0; nf < 4; nf++) {
#pragma unroll
        for (int i = 0; i < 2; i++) {
#pragma unroll
            for (int msk = 4; msk < 32; msk <<= 1) {
                ts[nf][i] += __shfl_xor_sync(0xFFFFFFFFu, ts[nf][i], msk);
                ts2[nf][i] += __shfl_xor_sync(0xFFFFFFFFu, ts2[nf][i], msk);
            }
        }
    }
    if (lane < 4) {
#pragma unroll
        for (int nf = 0; nf < 4; nf++) {
            int coll = wn * 32 + nf * 8 + lane * 2;
            sred[wm][coll][0] = ts[nf][0];
            sred[wm][coll][1] = ts2[nf][0];
            sred[wm][coll + 1][0] = ts[nf][1];
            sred[wm][coll + 1][1] = ts2[nf][1];
        }
    }
    __syncthreads();
    if (tid < 128) {
        float s = sred[0][tid][0] + sred[1][tid][0];
        float s2 = sred[0][tid][1] + sred[1][tid][1];
        int cg = blockIdx.x * 256 + n0 + tid;
        g_psum[cg] = s;
        g_psum2[cg] = s2;
    }
}

// ---------------- BatchNorm reduce (tiny) ----------------
__global__ void bn_reduce_kernel(const float* __restrict__ gamma, const float* __restrict__ beta) {
    int d = threadIdx.x;
    float s = 0, s2 = 0;
    for (int b = 0; b < NB_STAT; b++) {
        s += g_psum[b * DIM + d];
        s2 += g_psum2[b * DIM + d];
    }
    float mu = s / (float)NN;
    float var = s2 / (float)NN - mu * mu;
    float r = rsqrtf(var + EPS_BN);
    float a = gamma[d] * r;
    g_bn_a[d] = a;
    g_bn_b[d] = beta[d] - mu * a;
}

// relu(bn(h)) -> bf16 hi/lo split
__global__ void bnapply_kernel() {
    size_t e = (size_t)(blockIdx.x * blockDim.x + threadIdx.x) * 8;
    if (e >= (size_t)NN * DIM) return;
    int d = (int)(e & 255u);
    float4 v0 = *(const float4*)(g_h + e);
    float4 v1 = *(const float4*)(g_h + e + 4);
    float4 a0 = *(const float4*)(g_bn_a + d);
    float4 a1 = *(const float4*)(g_bn_a + d + 4);
    float4 b0 = *(const float4*)(g_bn_b + d);
    float4 b1 = *(const float4*)(g_bn_b + d + 4);
    float y[8];
    y[0] = fmaxf(v0.x * a0.x + b0.x, 0.f);
    y[1] = fmaxf(v0.y * a0.y + b0.y, 0.f);
    y[2] = fmaxf(v0.z * a0.z + b0.z, 0.f);
    y[3] = fmaxf(v0.w * a0.w + b0.w, 0.f);
    y[4] = fmaxf(v1.x * a1.x + b1.x, 0.f);
    y[5] = fmaxf(v1.y * a1.y + b1.y, 0.f);
    y[6] = fmaxf(v1.z * a1.z + b1.z, 0.f);
    y[7] = fmaxf(v1.w * a1.w + b1.w, 0.f);
    uint32_t h[4], l[4];
#pragma unroll
    for (int q = 0; q < 4; q++) split_pair(y[2 * q], y[2 * q + 1], h[q], l[q]);
    *(uint4*)(g_xh + e) = make_uint4(h[0], h[1], h[2], h[3]);
    *(uint4*)(g_xl + e) = make_uint4(l[0], l[1], l[2], l[3]);
}

// ---------------- fused tail: pool + 3-layer MLP, one block per graph --------
__device__ __forceinline__ int lower_bound_batch(const int* __restrict__ batch, int g) {
    int lo = 0, hi = NN;
    while (lo < hi) {
        int mid = (lo + hi) >> 1;
        if (batch[mid] < g) lo = mid + 1; else hi = mid;
    }
    return lo;
}

__global__ void tail_kernel(const int* __restrict__ batch,
                            const float* __restrict__ fc1_w, const float* __restrict__ fc1_b,
                            const float* __restrict__ fc2_w, const float* __restrict__ fc2_b,
                            const float* __restrict__ fc3_w, const float* __restrict__ fc3_b,
                            float* __restrict__ out) {
    __shared__ float xr[256];
    __shared__ float y1[128];
    __shared__ float y2[64];
    int g = blockIdx.x;
    int n = threadIdx.x;  // 256 threads
    int r0 = lower_bound_batch(batch, g);
    int r1 = lower_bound_batch(batch, g + 1);
    float s = 0;
#pragma unroll 4
    for (int r = r0; r < r1; r++) {
        size_t off = (size_t)r * DIM + n;
        s += __bfloat162float(g_xh[off]) + __bfloat162float(g_xl[off]);
    }
    int c = r1 - r0;
    xr[n] = s / (float)(c > 0 ? c : 1);
    __syncthreads();
    if (n < 128) {
        float t = fc1_b[n];
#pragma unroll 8
        for (int k = 0; k < 256; k++) t += xr[k] * fc1_w[k * 128 + n];
        y1[n] = fmaxf(t, 0.0f);
    }
    __syncthreads();
    if (n < 64) {
        float t = fc2_b[n];
#pragma unroll 8
        for (int k = 0; k < 128; k++) t += y1[k] * fc2_w[k * 64 + n];
        y2[n] = fmaxf(t, 0.0f);
    }
    __syncthreads();
    if (n < 10) {
        float t = fc3_b[n];
#pragma unroll 8
        for (int k = 0; k < 64; k++) t += y2[k] * fc3_w[k * 10 + n];
        out[g * 10 + n] = t;
    }
}

// ---------------- host launch ----------------
extern "C" void kernel_launch(void* const* d_in, const int* in_sizes, int n_in,
                              void* d_out, int out_size) {
    const float* x     = (const float*)d_in[0];
    const int*   ei    = (const int*)d_in[1];
    const int*   batch = (const int*)d_in[2];
    const float* Wl    = (const float*)d_in[3];
    const float* bl    = (const float*)d_in[4];
    const float* Wr    = (const float*)d_in[5];
    const float* gamma = (const float*)d_in[6];
    const float* beta  = (const float*)d_in[7];
    const float* fc1_w = (const float*)d_in[8];
    const float* fc1_b = (const float*)d_in[9];
    const float* fc2_w = (const float*)d_in[10];
    const float* fc2_b = (const float*)d_in[11];
    const float* fc3_w = (const float*)d_in[12];
    const float* fc3_b = (const float*)d_in[13];
    float* out = (float*)d_out;

    static bool attr_set = false;
    if (!attr_set) {
        cudaFuncSetAttribute(gemm_mma_kernel, cudaFuncAttributeMaxDynamicSharedMemorySize, GSM);
        cudaFuncSetAttribute(scan_kernel, cudaFuncAttributeMaxDynamicSharedMemorySize, NN * 4);
        attr_set = true;
    }

    // structure + conversions
    cvt_x_kernel<<<(NN * DIM / 8 + 255) / 256, 256>>>(x);   // also zeroes deg/fillpos
    deg_kernel<<<(NE + 255) / 256, 256>>>(ei);
    scan_kernel<<<1, 1024, NN * 4>>>();
    fill_kernel<<<(NE + 255) / 256, 256>>>(ei);
    reorder_kernel<<<(NN * 32 + 255) / 256, 256>>>();
    wtconv_kernel<<<dim3(16, 8, NLAYER), dim3(32, 32)>>>(Wl, Wr);

    for (int i = 0; i < NLAYER; i++) {
        gather_kernel<<<(NN * 32 + 255) / 256, 256>>>();
        gemm_mma_kernel<<<dim3(NN / MTILE, 2), 256, GSM>>>(i, bl + (size_t)i * DIM);
        bn_reduce_kernel<<<1, DIM>>>(gamma + (size_t)i * DIM, beta + (size_t)i * DIM);
        bnapply_kernel<<<(NN * DIM / 8 + 255) / 256, 256>>>();
    }

    tail_kernel<<<NG, 256>>>(batch, fc1_w, fc1_b, fc2_w, fc2_b, fc3_w, fc3_b, out);
}

// round 13
// speedup vs baseline: 2.1245x; 1.0083x over previous
#include <cuda_runtime.h>
#include <cuda_bf16.h>
#include <cstdint>

#define NN 20000
#define NE 320000
#define NG 256
#define DIM 256
#define NLAYER 4
#define EPS_BN 1e-5f
#define MTILE 160
#define NB_STAT 125   // 20000/160 = gemm grid.x (exact)

// ---------------- device scratch (static, no allocation) ----------------
__device__ __align__(16) float g_h[(size_t)NN * DIM];
__device__ __align__(16) __nv_bfloat16 g_xh[(size_t)NN * DIM];
__device__ __align__(16) __nv_bfloat16 g_xl[(size_t)NN * DIM];
__device__ __align__(16) __nv_bfloat16 g_aggh[(size_t)NN * DIM];
__device__ __align__(16) __nv_bfloat16 g_aggl[(size_t)NN * DIM];
__device__ float g_invdeg[NN];
__device__ int   g_deg[NN];
__device__ int   g_fillpos[NN];
__device__ int   g_rowptr[NN + 1];
__device__ int   g_colidx[NE];
__device__ int   g_colidx2[NE];
__device__ float g_psum[NB_STAT * DIM];
__device__ float g_psum2[NB_STAT * DIM];
__device__ float g_bn_a[DIM];
__device__ float g_bn_b[DIM];
// transposed + bf16-split weights: [L][2(hi/lo)][256 n][512 k]
__device__ __align__(16) __nv_bfloat16 g_wt[(size_t)NLAYER * 2 * 256 * 512];

__device__ __forceinline__ uint32_t smem_u32(const void* p) {
    uint32_t a;
    asm("{ .reg .u64 t; cvta.to.shared.u64 t, %1; cvt.u32.u64 %0, t; }" : "=r"(a) : "l"(p));
    return a;
}

__device__ __forceinline__ void split_pair(float x, float y, uint32_t& h, uint32_t& l) {
    __nv_bfloat162 hb = __floats2bfloat162_rn(x, y);
    float hx = __low2float(hb), hy = __high2float(hb);
    __nv_bfloat162 lb = __floats2bfloat162_rn(x - hx, y - hy);
    h = *reinterpret_cast<uint32_t*>(&hb);
    l = *reinterpret_cast<uint32_t*>(&lb);
}

// ---------------- input conversion (+ zero of structure counters) ------------
__global__ void cvt_x_kernel(const float* __restrict__ x) {
    int t = blockIdx.x * blockDim.x + threadIdx.x;
    if (t < NN) { g_deg[t] = 0; g_fillpos[t] = 0; }
    size_t e = (size_t)t * 8;
    if (e >= (size_t)NN * DIM) return;
    float4 v0 = *(const float4*)(x + e);
    float4 v1 = *(const float4*)(x + e + 4);
    uint32_t h[4], l[4];
    split_pair(v0.x, v0.y, h[0], l[0]);
    split_pair(v0.z, v0.w, h[1], l[1]);
    split_pair(v1.x, v1.y, h[2], l[2]);
    split_pair(v1.z, v1.w, h[3], l[3]);
    *(uint4*)(g_xh + e) = make_uint4(h[0], h[1], h[2], h[3]);
    *(uint4*)(g_xl + e) = make_uint4(l[0], l[1], l[2], l[3]);
}

// ---------------- graph structure build ----------------
__global__ void deg_kernel(const int* __restrict__ ei) {
    int e = blockIdx.x * blockDim.x + threadIdx.x;
    if (e >= NE) return;
    atomicAdd(&g_deg[ei[NE + e]], 1);
}

// single-block scan (smem-staged), also emits invdeg. 1024 threads.
__global__ void scan_kernel() {
    extern __shared__ int sdeg[];
    __shared__ int wsum[32];
    int tid = threadIdx.x;
    for (int i = tid; i < NN; i += 1024) {
        int d = g_deg[i];
        sdeg[i] = d;
        g_invdeg[i] = (d > 0) ? 1.0f / (float)d : 0.0f;
    }
    __syncthreads();
    const int PER = 20;  // 1024*20 = 20480 >= NN
    int i0 = tid * PER;
    int s = 0;
#pragma unroll 4
    for (int j = 0; j < PER; j++) {
        int i = i0 + j;
        if (i < NN) s += sdeg[i];
    }
    int lane = tid & 31, warp = tid >> 5;
    int inc = s;
    for (int off = 1; off < 32; off <<= 1) {
        int t = __shfl_up_sync(0xFFFFFFFFu, inc, off);
        if (lane >= off) inc += t;
    }
    if (lane == 31) wsum[warp] = inc;
    __syncthreads();
    if (warp == 0) {
        int v = wsum[lane];
        for (int off = 1; off < 32; off <<= 1) {
            int t = __shfl_up_sync(0xFFFFFFFFu, v, off);
            if (lane >= off) v += t;
        }
        wsum[lane] = v;
    }
    __syncthreads();
    int prefix = inc - s + (warp > 0 ? wsum[warp - 1] : 0);  // exclusive
    int run = prefix;
    for (int j = 0; j < PER; j++) {
        int i = i0 + j;
        if (i < NN) { int d = sdeg[i]; sdeg[i] = run; run += d; }
    }
    if (tid == 1023) g_rowptr[NN] = run;
    __syncthreads();
    for (int i = tid; i < NN; i += 1024) g_rowptr[i] = sdeg[i];
}

__global__ void fill_kernel(const int* __restrict__ ei) {
    int e = blockIdx.x * blockDim.x + threadIdx.x;
    if (e >= NE) return;
    int src = ei[e];
    int dst = ei[NE + e];
    int p = atomicAdd(&g_fillpos[dst], 1);
    g_colidx[g_rowptr[dst] + p] = src;
}

// warp-parallel stable rank sort per adjacency list (deterministic sum order)
__global__ void reorder_kernel() {
    int warp = (blockIdx.x * blockDim.x + threadIdx.x) >> 5;
    int lane = threadIdx.x & 31;
    if (warp >= NN) return;
    int b = g_rowptr[warp], e = g_rowptr[warp + 1];
    int d = e - b;
    for (int i = lane; i < d; i += 32) {
        int key = g_colidx[b + i];
        int rank = 0;
        for (int j = 0; j < d; j++) {
            int kj = g_colidx[b + j];
            rank += (kj < key) || (kj == key && j < i);
        }
        g_colidx2[b + rank] = key;
    }
}

// ---------------- weight transpose + bf16 split ----------------
__global__ void wtconv_kernel(const float* __restrict__ Wl, const float* __restrict__ Wr) {
    __shared__ float t[32][33];
    int L = blockIdx.z, k0 = blockIdx.x * 32, n0 = blockIdx.y * 32;
    int tx = threadIdx.x, ty = threadIdx.y;
    const float* W = (k0 < 256) ? (Wl + (size_t)L * 65536 + (size_t)k0 * 256)
                                : (Wr + (size_t)L * 65536 + (size_t)(k0 - 256) * 256);
    t[ty][tx] = W[(size_t)ty * 256 + n0 + tx];
    __syncthreads();
    float v = t[tx][ty];  // = W[k0+tx][n0+ty]
    int n = n0 + ty, k = k0 + tx;
    __nv_bfloat16 hb = __float2bfloat16(v);
    __nv_bfloat16 lb = __float2bfloat16(v - __bfloat162float(hb));
    size_t base = (size_t)L * 262144;
    g_wt[base + (size_t)n * 512 + k] = hb;
    g_wt[base + 131072 + (size_t)n * 512 + k] = lb;
}

// -------- mean aggregation (warp per node) fused with BN+ReLU+split ---------
// USE_BN=false: neighbors read from xext (layer 0 input), raw values.
// USE_BN=true:  neighbors read from g_h with bn_a*v+bn_b then ReLU applied;
//               also writes this node's xh/xl = split(relu(bn(h[node]))).
template <bool USE_BN>
__global__ void gather_kernel(const float* __restrict__ xext) {
    int warp = (blockIdx.x * blockDim.x + threadIdx.x) >> 5;
    int lane = threadIdx.x & 31;
    if (warp >= NN) return;
    const float* src = USE_BN ? (const float*)g_h : xext;
    int b = g_rowptr[warp], e = g_rowptr[warp + 1];
    int col = lane * 8;
    float bna[8], bnb[8];
    if (USE_BN) {
        float4 a0 = *(const float4*)(g_bn_a + col);
        float4 a1 = *(const float4*)(g_bn_a + col + 4);
        float4 c0 = *(const float4*)(g_bn_b + col);
        float4 c1 = *(const float4*)(g_bn_b + col + 4);
        bna[0] = a0.x; bna[1] = a0.y; bna[2] = a0.z; bna[3] = a0.w;
        bna[4] = a1.x; bna[5] = a1.y; bna[6] = a1.z; bna[7] = a1.w;
        bnb[0] = c0.x; bnb[1] = c0.y; bnb[2] = c0.z; bnb[3] = c0.w;
        bnb[4] = c1.x; bnb[5] = c1.y; bnb[6] = c1.z; bnb[7] = c1.w;
    }
    float acc[8] = {0, 0, 0, 0, 0, 0, 0, 0};
    for (int j = b; j < e; j++) {
        int u = g_colidx2[j];
        const float4* p = (const float4*)(src + (size_t)u * DIM + col);
        float4 v0 = p[0], v1 = p[1];
        float v[8] = {v0.x, v0.y, v0.z, v0.w, v1.x, v1.y, v1.z, v1.w};
#pragma unroll
        for (int q = 0; q < 8; q++) {
            float t = USE_BN ? fmaxf(v[q] * bna[q] + bnb[q], 0.f) : v[q];
            acc[q] += t;
        }
    }
    float s = g_invdeg[warp];
    uint32_t h[4], l[4];
#pragma unroll
    for (int q = 0; q < 4; q++) split_pair(acc[2 * q] * s, acc[2 * q + 1] * s, h[q], l[q]);
    size_t off = (size_t)warp * DIM + col;
    *(uint4*)(g_aggh + off) = make_uint4(h[0], h[1], h[2], h[3]);
    *(uint4*)(g_aggl + off) = make_uint4(l[0], l[1], l[2], l[3]);
    if (USE_BN) {
        const float4* p = (const float4*)(src + off);
        float4 v0 = p[0], v1 = p[1];
        float v[8] = {v0.x, v0.y, v0.z, v0.w, v1.x, v1.y, v1.z, v1.w};
        uint32_t hh[4], ll[4];
#pragma unroll
        for (int q = 0; q < 4; q++) {
            float y0 = fmaxf(v[2 * q] * bna[2 * q] + bnb[2 * q], 0.f);
            float y1 = fmaxf(v[2 * q + 1] * bna[2 * q + 1] + bnb[2 * q + 1], 0.f);
            split_pair(y0, y1, hh[q], ll[q]);
        }
        *(uint4*)(g_xh + off) = make_uint4(hh[0], hh[1], hh[2], hh[3]);
        *(uint4*)(g_xl + off) = make_uint4(ll[0], ll[1], ll[2], ll[3]);
    }
}

// ---------------- pipelined mma.sync GEMM + fused BN stats -------------------
#define AHI 0
#define ALO 12800
#define BHI 25600
#define BLO 35840
#define STAGE 46080
#define GSM (2 * STAGE)

#define CPA(dst, src, sz) \
    asm volatile("cp.async.cg.shared.global [%0], [%1], 16, %2;" \
        :: "r"(dst), "l"(src), "r"(sz) : "memory")
#define CPC() asm volatile("cp.async.commit_group;" ::: "memory")
#define CPW(n) asm volatile("cp.async.wait_group %0;" :: "n"(n) : "memory")

#define LDSM4(r, addr) \
    asm volatile("ldmatrix.sync.aligned.m8n8.x4.shared.b16 {%0,%1,%2,%3}, [%4];" \
        : "=r"((r)[0]), "=r"((r)[1]), "=r"((r)[2]), "=r"((r)[3]) : "r"(addr))

#define MMA16816(c, a, b0_, b1_) \
    asm volatile("mma.sync.aligned.m16n8k16.row.col.f32.bf16.bf16.f32 " \
        "{%0,%1,%2,%3}, {%4,%5,%6,%7}, {%8,%9}, {%0,%1,%2,%3};" \
        : "+f"((c)[0]), "+f"((c)[1]), "+f"((c)[2]), "+f"((c)[3]) \
        : "r"((a)[0]), "r"((a)[1]), "r"((a)[2]), "r"((a)[3]), "r"(b0_), "r"(b1_))

__device__ __forceinline__ void load_stage(int s, uint32_t sb, int m0,
                                           const __nv_bfloat16* wtL) {
    const __nv_bfloat16* Ah = (s < 8) ? g_aggh : g_xh;
    const __nv_bfloat16* Al = (s < 8) ? g_aggl : g_xl;
    int kg = (s & 7) * 32;
    int tid = threadIdx.x;
#pragma unroll
    for (int i = 0; i < 3; i++) {
        int idx = tid + i * 256;
        if (idx < 640) {
            int row = idx >> 2, q = idx & 3;
            size_t so = (size_t)(m0 + row) * 256 + kg + q * 8;
            uint32_t off = (uint32_t)row * 80 + q * 16;
            CPA(sb + AHI + off, Ah + so, 16u);
            CPA(sb + ALO + off, Al + so, 16u);
        }
    }
#pragma unroll
    for (int i = 0; i < 2; i++) {
        int idx = tid + i * 256;
        int row = idx >> 2, q = idx & 3;
        const __nv_bfloat16* src = wtL + (size_t)row * 512 + s * 32 + q * 8;
        uint32_t off = (uint32_t)row * 80 + q * 16;
        CPA(sb + BHI + off, src, 16u);
        CPA(sb + BLO + off, src + 131072, 16u);
    }
}

__global__ void __launch_bounds__(256, 2)
gemm_mma_kernel(int layer, const float* __restrict__ bl_) {
    extern __shared__ char sm[];
    __shared__ float sred[2][128][2];  // [wm][local col][{sum, sumsq}]
    uint32_t sb = smem_u32(sm);
    int tid = threadIdx.x;
    int lane = tid & 31, wid = tid >> 5;
    int wm = wid >> 2, wn = wid & 3;           // warp tile: 80(M) x 32(N)
    int m0 = blockIdx.x * MTILE, n0 = blockIdx.y * 128;
    const __nv_bfloat16* wtL = g_wt + (size_t)layer * 262144 + (size_t)n0 * 512;

    float C[5][4][4];
#pragma unroll
    for (int i = 0; i < 5; i++)
#pragma unroll
        for (int j = 0; j < 4; j++)
#pragma unroll
            for (int q = 0; q < 4; q++) C[i][j][q] = 0.0f;

    uint32_t a_row = (uint32_t)(wm * 80 + (lane & 15));
    uint32_t a_koff = (uint32_t)((lane >> 4) * 8);
    uint32_t b_row = (uint32_t)(wn * 32 + ((lane >> 4) & 1) * 8 + (lane & 7));
    uint32_t b_koff = (uint32_t)(((lane >> 3) & 1) * 8);

    load_stage(0, sb, m0, wtL);
    CPC();

    for (int s = 0; s < 16; s++) {
        if (s < 15) {
            load_stage(s + 1, sb + ((uint32_t)(s + 1) & 1u) * STAGE, m0, wtL);
            CPC();
            CPW(1);
        } else {
            CPW(0);
        }
        __syncthreads();
        uint32_t bufb = sb + ((uint32_t)s & 1u) * STAGE;
#pragma unroll
        for (int kl = 0; kl < 32; kl += 16) {
            uint32_t bh[2][4], blo_[2][4];
#pragma unroll
            for (int nf16 = 0; nf16 < 2; nf16++) {
                uint32_t ro = (b_row + nf16 * 16) * 80 + (b_koff + kl) * 2;
                LDSM4(bh[nf16], bufb + BHI + ro);
                LDSM4(blo_[nf16], bufb + BLO + ro);
            }
#pragma unroll
            for (int mf = 0; mf < 5; mf++) {
                uint32_t ah[4], al[4];
                uint32_t ro = (a_row + mf * 16) * 80 + (a_koff + kl) * 2;
                LDSM4(ah, bufb + AHI + ro);
                LDSM4(al, bufb + ALO + ro);
#pragma unroll
                for (int nf = 0; nf < 4; nf++) {
                    uint32_t b0 = bh[nf >> 1][(nf & 1) * 2];
                    uint32_t b1 = bh[nf >> 1][(nf & 1) * 2 + 1];
                    uint32_t lb0 = blo_[nf >> 1][(nf & 1) * 2];
                    uint32_t lb1 = blo_[nf >> 1][(nf & 1) * 2 + 1];
                    MMA16816(C[mf][nf], ah, b0, b1);
                    MMA16816(C[mf][nf], al, b0, b1);
                    MMA16816(C[mf][nf], ah, lb0, lb1);
                }
            }
        }
        __syncthreads();
    }
    // ---- epilogue: bias + store + fused BN stats (rows always in-range) ----
    int mbase = m0 + wm * 80;
    int nbase = n0 + wn * 32;
    float ts[4][2], ts2[4][2];
#pragma unroll
    for (int nf = 0; nf < 4; nf++) {
        ts[nf][0] = ts[nf][1] = 0.f;
        ts2[nf][0] = ts2[nf][1] = 0.f;
    }
#pragma unroll
    for (int mf = 0; mf < 5; mf++) {
#pragma unroll
        for (int nf = 0; nf < 4; nf++) {
            int c = nbase + nf * 8 + (lane & 3) * 2;
            float bv0 = bl_[c], bv1 = bl_[c + 1];
            int r0 = mbase + mf * 16 + (lane >> 2);
            {
                float ox = C[mf][nf][0] + bv0, oy = C[mf][nf][1] + bv1;
                *(float2*)(g_h + (size_t)r0 * 256 + c) = make_float2(ox, oy);
                ts[nf][0] += ox; ts2[nf][0] += ox * ox;
                ts[nf][1] += oy; ts2[nf][1] += oy * oy;
            }
            {
                int r1 = r0 + 8;
                float ox = C[mf][nf][2] + bv0, oy = C[mf][nf][3] + bv1;
                *(float2*)(g_h + (size_t)r1 * 256 + c) = make_float2(ox, oy);
                ts[nf][0] += ox; ts2[nf][0] += ox * ox;
                ts[nf][1] += oy; ts2[nf][1] += oy * oy;
            }
        }
    }
#pragma unroll
    for (int nf = 0; nf < 4; nf++) {
#pragma unroll
        for (int i = 0; i < 2; i++) {
#pragma unroll
            for (int msk = 4; msk < 32; msk <<= 1) {
                ts[nf][i] += __shfl_xor_sync(0xFFFFFFFFu, ts[nf][i], msk);
                ts2[nf][i] += __shfl_xor_sync(0xFFFFFFFFu, ts2[nf][i], msk);
            }
        }
    }
    if (lane < 4) {
#pragma unroll
        for (int nf = 0; nf < 4; nf++) {
            int coll = wn * 32 + nf * 8 + lane * 2;
            sred[wm][coll][0] = ts[nf][0];
            sred[wm][coll][1] = ts2[nf][0];
            sred[wm][coll + 1][0] = ts[nf][1];
            sred[wm][coll + 1][1] = ts2[nf][1];
        }
    }
    __syncthreads();
    if (tid < 128) {
        float s = sred[0][tid][0] + sred[1][tid][0];
        float s2 = sred[0][tid][1] + sred[1][tid][1];
        int cg = blockIdx.x * 256 + n0 + tid;
        g_psum[cg] = s;
        g_psum2[cg] = s2;
    }
}

// ---------------- BatchNorm reduce (tiny) ----------------
__global__ void bn_reduce_kernel(const float* __restrict__ gamma, const float* __restrict__ beta) {
    int d = threadIdx.x;
    float s = 0, s2 = 0;
    for (int b = 0; b < NB_STAT; b++) {
        s += g_psum[b * DIM + d];
        s2 += g_psum2[b * DIM + d];
    }
    float mu = s / (float)NN;
    float var = s2 / (float)NN - mu * mu;
    float r = rsqrtf(var + EPS_BN);
    float a = gamma[d] * r;
    g_bn_a[d] = a;
    g_bn_b[d] = beta[d] - mu * a;
}

// ---------------- fused tail: pool(bn+relu of h) + 3-layer MLP ---------------
__device__ __forceinline__ int lower_bound_batch(const int* __restrict__ batch, int g) {
    int lo = 0, hi = NN;
    while (lo < hi) {
        int mid = (lo + hi) >> 1;
        if (batch[mid] < g) lo = mid + 1; else hi = mid;
    }
    return lo;
}

__global__ void tail_kernel(const int* __restrict__ batch,
                            const float* __restrict__ fc1_w, const float* __restrict__ fc1_b,
                            const float* __restrict__ fc2_w, const float* __restrict__ fc2_b,
                            const float* __restrict__ fc3_w, const float* __restrict__ fc3_b,
                            float* __restrict__ out) {
    __shared__ float xr[256];
    __shared__ float y1[128];
    __shared__ float y2[64];
    int g = blockIdx.x;
    int n = threadIdx.x;  // 256 threads
    int r0 = lower_bound_batch(batch, g);
    int r1 = lower_bound_batch(batch, g + 1);
    float ba = g_bn_a[n], bb = g_bn_b[n];
    float s = 0;
#pragma unroll 4
    for (int r = r0; r < r1; r++) {
        float v = g_h[(size_t)r * DIM + n];
        s += fmaxf(v * ba + bb, 0.f);
    }
    int c = r1 - r0;
    xr[n] = s / (float)(c > 0 ? c : 1);
    __syncthreads();
    if (n < 128) {
        float t = fc1_b[n];
#pragma unroll 8
        for (int k = 0; k < 256; k++) t += xr[k] * fc1_w[k * 128 + n];
        y1[n] = fmaxf(t, 0.0f);
    }
    __syncthreads();
    if (n < 64) {
        float t = fc2_b[n];
#pragma unroll 8
        for (int k = 0; k < 128; k++) t += y1[k] * fc2_w[k * 64 + n];
        y2[n] = fmaxf(t, 0.0f);
    }
    __syncthreads();
    if (n < 10) {
        float t = fc3_b[n];
#pragma unroll 8
        for (int k = 0; k < 64; k++) t += y2[k] * fc3_w[k * 10 + n];
        out[g * 10 + n] = t;
    }
}

// ---------------- host launch ----------------
extern "C" void kernel_launch(void* const* d_in, const int* in_sizes, int n_in,
                              void* d_out, int out_size) {
    const float* x     = (const float*)d_in[0];
    const int*   ei    = (const int*)d_in[1];
    const int*   batch = (const int*)d_in[2];
    const float* Wl    = (const float*)d_in[3];
    const float* bl    = (const float*)d_in[4];
    const float* Wr    = (const float*)d_in[5];
    const float* gamma = (const float*)d_in[6];
    const float* beta  = (const float*)d_in[7];
    const float* fc1_w = (const float*)d_in[8];
    const float* fc1_b = (const float*)d_in[9];
    const float* fc2_w = (const float*)d_in[10];
    const float* fc2_b = (const float*)d_in[11];
    const float* fc3_w = (const float*)d_in[12];
    const float* fc3_b = (const float*)d_in[13];
    float* out = (float*)d_out;

    static bool attr_set = false;
    if (!attr_set) {
        cudaFuncSetAttribute(gemm_mma_kernel, cudaFuncAttributeMaxDynamicSharedMemorySize, GSM);
        cudaFuncSetAttribute(scan_kernel, cudaFuncAttributeMaxDynamicSharedMemorySize, NN * 4);
        attr_set = true;
    }

    // structure + conversions
    cvt_x_kernel<<<(NN * DIM / 8 + 255) / 256, 256>>>(x);   // also zeroes deg/fillpos
    deg_kernel<<<(NE + 255) / 256, 256>>>(ei);
    scan_kernel<<<1, 1024, NN * 4>>>();
    fill_kernel<<<(NE + 255) / 256, 256>>>(ei);
    reorder_kernel<<<(NN * 32 + 255) / 256, 256>>>();
    wtconv_kernel<<<dim3(16, 8, NLAYER), dim3(32, 32)>>>(Wl, Wr);

    for (int i = 0; i < NLAYER; i++) {
        if (i == 0)
            gather_kernel<false><<<(NN * 32 + 255) / 256, 256>>>(x);
        else
            gather_kernel<true><<<(NN * 32 + 255) / 256, 256>>>(nullptr);
        gemm_mma_kernel<<<dim3(NN / MTILE, 2), 256, GSM>>>(i, bl + (size_t)i * DIM);
        bn_reduce_kernel<<<1, DIM>>>(gamma + (size_t)i * DIM, beta + (size_t)i * DIM);
    }

    tail_kernel<<<NG, 256>>>(batch, fc1_w, fc1_b, fc2_w, fc2_b, fc3_w, fc3_b, out);
}

// round 15
// speedup vs baseline: 2.4785x; 1.1667x over previous
#include <cuda_runtime.h>
#include <cuda_bf16.h>
#include <cstdint>

#define NN 20000
#define NE 320000
#define NG 256
#define DIM 256
#define NLAYER 4
#define EPS_BN 1e-5f
#define MTILE 160
#define NB_STAT 125   // 20000/160 = gemm grid.x (exact)

// ---------------- device scratch (static, no allocation) ----------------
__device__ __align__(16) float g_h[(size_t)NN * DIM];
__device__ __align__(16) __nv_bfloat16 g_xh[(size_t)NN * DIM];
__device__ __align__(16) __nv_bfloat16 g_xl[(size_t)NN * DIM];
__device__ __align__(16) __nv_bfloat16 g_aggh[(size_t)NN * DIM];
__device__ __align__(16) __nv_bfloat16 g_aggl[(size_t)NN * DIM];
__device__ float g_invdeg[NN];
__device__ int   g_deg[NN];
__device__ int   g_fillpos[NN];
__device__ int   g_rowptr[NN + 1];
__device__ int   g_colidx[NE];
__device__ int   g_colidx2[NE];
__device__ float g_psum[NB_STAT * DIM];
__device__ float g_psum2[NB_STAT * DIM];
__device__ float g_bn_a[DIM];
__device__ float g_bn_b[DIM];
__device__ int   g_ctr[NLAYER];
// transposed + bf16-split weights: [L][2(hi/lo)][256 n][512 k] (lo unused now)
__device__ __align__(16) __nv_bfloat16 g_wt[(size_t)NLAYER * 2 * 256 * 512];

__device__ __forceinline__ uint32_t smem_u32(const void* p) {
    uint32_t a;
    asm("{ .reg .u64 t; cvta.to.shared.u64 t, %1; cvt.u32.u64 %0, t; }" : "=r"(a) : "l"(p));
    return a;
}

__device__ __forceinline__ void split_pair(float x, float y, uint32_t& h, uint32_t& l) {
    __nv_bfloat162 hb = __floats2bfloat162_rn(x, y);
    float hx = __low2float(hb), hy = __high2float(hb);
    __nv_bfloat162 lb = __floats2bfloat162_rn(x - hx, y - hy);
    h = *reinterpret_cast<uint32_t*>(&hb);
    l = *reinterpret_cast<uint32_t*>(&lb);
}

// ---------------- input conversion (+ zero of structure counters) ------------
__global__ void cvt_x_kernel(const float* __restrict__ x) {
    int t = blockIdx.x * blockDim.x + threadIdx.x;
    if (t < NN) { g_deg[t] = 0; g_fillpos[t] = 0; }
    if (t < NLAYER) g_ctr[t] = 0;
    size_t e = (size_t)t * 8;
    if (e >= (size_t)NN * DIM) return;
    float4 v0 = *(const float4*)(x + e);
    float4 v1 = *(const float4*)(x + e + 4);
    uint32_t h[4], l[4];
    split_pair(v0.x, v0.y, h[0], l[0]);
    split_pair(v0.z, v0.w, h[1], l[1]);
    split_pair(v1.x, v1.y, h[2], l[2]);
    split_pair(v1.z, v1.w, h[3], l[3]);
    *(uint4*)(g_xh + e) = make_uint4(h[0], h[1], h[2], h[3]);
    *(uint4*)(g_xl + e) = make_uint4(l[0], l[1], l[2], l[3]);
}

// ---------------- graph structure build ----------------
__global__ void deg_kernel(const int* __restrict__ ei) {
    int e = blockIdx.x * blockDim.x + threadIdx.x;
    if (e >= NE) return;
    atomicAdd(&g_deg[ei[NE + e]], 1);
}

// single-block scan (smem-staged), also emits invdeg. 1024 threads.
__global__ void scan_kernel() {
    extern __shared__ int sdeg[];
    __shared__ int wsum[32];
    int tid = threadIdx.x;
    for (int i = tid; i < NN; i += 1024) {
        int d = g_deg[i];
        sdeg[i] = d;
        g_invdeg[i] = (d > 0) ? 1.0f / (float)d : 0.0f;
    }
    __syncthreads();
    const int PER = 20;  // 1024*20 = 20480 >= NN
    int i0 = tid * PER;
    int s = 0;
#pragma unroll 4
    for (int j = 0; j < PER; j++) {
        int i = i0 + j;
        if (i < NN) s += sdeg[i];
    }
    int lane = tid & 31, warp = tid >> 5;
    int inc = s;
    for (int off = 1; off < 32; off <<= 1) {
        int t = __shfl_up_sync(0xFFFFFFFFu, inc, off);
        if (lane >= off) inc += t;
    }
    if (lane == 31) wsum[warp] = inc;
    __syncthreads();
    if (warp == 0) {
        int v = wsum[lane];
        for (int off = 1; off < 32; off <<= 1) {
            int t = __shfl_up_sync(0xFFFFFFFFu, v, off);
            if (lane >= off) v += t;
        }
        wsum[lane] = v;
    }
    __syncthreads();
    int prefix = inc - s + (warp > 0 ? wsum[warp - 1] : 0);  // exclusive
    int run = prefix;
    for (int j = 0; j < PER; j++) {
        int i = i0 + j;
        if (i < NN) { int d = sdeg[i]; sdeg[i] = run; run += d; }
    }
    if (tid == 1023) g_rowptr[NN] = run;
    __syncthreads();
    for (int i = tid; i < NN; i += 1024) g_rowptr[i] = sdeg[i];
}

__global__ void fill_kernel(const int* __restrict__ ei) {
    int e = blockIdx.x * blockDim.x + threadIdx.x;
    if (e >= NE) return;
    int src = ei[e];
    int dst = ei[NE + e];
    int p = atomicAdd(&g_fillpos[dst], 1);
    g_colidx[g_rowptr[dst] + p] = src;
}

// warp-parallel stable rank sort per adjacency list (deterministic sum order)
__global__ void reorder_kernel() {
    int warp = (blockIdx.x * blockDim.x + threadIdx.x) >> 5;
    int lane = threadIdx.x & 31;
    if (warp >= NN) return;
    int b = g_rowptr[warp], e = g_rowptr[warp + 1];
    int d = e - b;
    for (int i = lane; i < d; i += 32) {
        int key = g_colidx[b + i];
        int rank = 0;
        for (int j = 0; j < d; j++) {
            int kj = g_colidx[b + j];
            rank += (kj < key) || (kj == key && j < i);
        }
        g_colidx2[b + rank] = key;
    }
}

// ---------------- weight transpose + bf16 (hi only used) ----------------
__global__ void wtconv_kernel(const float* __restrict__ Wl, const float* __restrict__ Wr) {
    __shared__ float t[32][33];
    int L = blockIdx.z, k0 = blockIdx.x * 32, n0 = blockIdx.y * 32;
    int tx = threadIdx.x, ty = threadIdx.y;
    const float* W = (k0 < 256) ? (Wl + (size_t)L * 65536 + (size_t)k0 * 256)
                                : (Wr + (size_t)L * 65536 + (size_t)(k0 - 256) * 256);
    t[ty][tx] = W[(size_t)ty * 256 + n0 + tx];
    __syncthreads();
    float v = t[tx][ty];  // = W[k0+tx][n0+ty]
    int n = n0 + ty, k = k0 + tx;
    __nv_bfloat16 hb = __float2bfloat16(v);
    size_t base = (size_t)L * 262144;
    g_wt[base + (size_t)n * 512 + k] = hb;
}

// -------- mean aggregation (warp per node) fused with BN+ReLU+split ---------
template <bool USE_BN>
__global__ void gather_kernel(const float* __restrict__ xext) {
    int warp = (blockIdx.x * blockDim.x + threadIdx.x) >> 5;
    int lane = threadIdx.x & 31;
    if (warp >= NN) return;
    const float* src = USE_BN ? (const float*)g_h : xext;
    int b = g_rowptr[warp], e = g_rowptr[warp + 1];
    int col = lane * 8;
    float bna[8], bnb[8];
    if (USE_BN) {
        float4 a0 = *(const float4*)(g_bn_a + col);
        float4 a1 = *(const float4*)(g_bn_a + col + 4);
        float4 c0 = *(const float4*)(g_bn_b + col);
        float4 c1 = *(const float4*)(g_bn_b + col + 4);
        bna[0] = a0.x; bna[1] = a0.y; bna[2] = a0.z; bna[3] = a0.w;
        bna[4] = a1.x; bna[5] = a1.y; bna[6] = a1.z; bna[7] = a1.w;
        bnb[0] = c0.x; bnb[1] = c0.y; bnb[2] = c0.z; bnb[3] = c0.w;
        bnb[4] = c1.x; bnb[5] = c1.y; bnb[6] = c1.z; bnb[7] = c1.w;
    }
    float acc[8] = {0, 0, 0, 0, 0, 0, 0, 0};
    for (int j = b; j < e; j++) {
        int u = g_colidx2[j];
        const float4* p = (const float4*)(src + (size_t)u * DIM + col);
        float4 v0 = p[0], v1 = p[1];
        float v[8] = {v0.x, v0.y, v0.z, v0.w, v1.x, v1.y, v1.z, v1.w};
#pragma unroll
        for (int q = 0; q < 8; q++) {
            float t = USE_BN ? fmaxf(v[q] * bna[q] + bnb[q], 0.f) : v[q];
            acc[q] += t;
        }
    }
    float s = g_invdeg[warp];
    uint32_t h[4], l[4];
#pragma unroll
    for (int q = 0; q < 4; q++) split_pair(acc[2 * q] * s, acc[2 * q + 1] * s, h[q], l[q]);
    size_t off = (size_t)warp * DIM + col;
    *(uint4*)(g_aggh + off) = make_uint4(h[0], h[1], h[2], h[3]);
    *(uint4*)(g_aggl + off) = make_uint4(l[0], l[1], l[2], l[3]);
    if (USE_BN) {
        const float4* p = (const float4*)(src + off);
        float4 v0 = p[0], v1 = p[1];
        float v[8] = {v0.x, v0.y, v0.z, v0.w, v1.x, v1.y, v1.z, v1.w};
        uint32_t hh[4], ll[4];
#pragma unroll
        for (int q = 0; q < 4; q++) {
            float y0 = fmaxf(v[2 * q] * bna[2 * q] + bnb[2 * q], 0.f);
            float y1 = fmaxf(v[2 * q + 1] * bna[2 * q + 1] + bnb[2 * q + 1], 0.f);
            split_pair(y0, y1, hh[q], ll[q]);
        }
        *(uint4*)(g_xh + off) = make_uint4(hh[0], hh[1], hh[2], hh[3]);
        *(uint4*)(g_xl + off) = make_uint4(ll[0], ll[1], ll[2], ll[3]);
    }
}

// ---------- pipelined mma.sync GEMM + fused BN stats + fused bn_reduce -------
// block 160(M) x 128(N), 8 warps each 80x32, K=512 in 16 stages of 32.
// per stage (35840 B): Ahi@0 (160x32 bf16, stride 80B), Alo@12800, Bhi@25600.
#define AHI 0
#define ALO 12800
#define BHI 25600
#define STAGE 35840
#define GSM (2 * STAGE)

#define CPA(dst, src, sz) \
    asm volatile("cp.async.cg.shared.global [%0], [%1], 16, %2;" \
        :: "r"(dst), "l"(src), "r"(sz) : "memory")
#define CPC() asm volatile("cp.async.commit_group;" ::: "memory")
#define CPW(n) asm volatile("cp.async.wait_group %0;" :: "n"(n) : "memory")

#define LDSM4(r, addr) \
    asm volatile("ldmatrix.sync.aligned.m8n8.x4.shared.b16 {%0,%1,%2,%3}, [%4];" \
        : "=r"((r)[0]), "=r"((r)[1]), "=r"((r)[2]), "=r"((r)[3]) : "r"(addr))

#define MMA16816(c, a, b0_, b1_) \
    asm volatile("mma.sync.aligned.m16n8k16.row.col.f32.bf16.bf16.f32 " \
        "{%0,%1,%2,%3}, {%4,%5,%6,%7}, {%8,%9}, {%0,%1,%2,%3};" \
        : "+f"((c)[0]), "+f"((c)[1]), "+f"((c)[2]), "+f"((c)[3]) \
        : "r"((a)[0]), "r"((a)[1]), "r"((a)[2]), "r"((a)[3]), "r"(b0_), "r"(b1_))

__device__ __forceinline__ void load_stage(int s, uint32_t sb, int m0,
                                           const __nv_bfloat16* wtL) {
    const __nv_bfloat16* Ah = (s < 8) ? g_aggh : g_xh;
    const __nv_bfloat16* Al = (s < 8) ? g_aggl : g_xl;
    int kg = (s & 7) * 32;
    int tid = threadIdx.x;
#pragma unroll
    for (int i = 0; i < 3; i++) {
        int idx = tid + i * 256;
        if (idx < 640) {
            int row = idx >> 2, q = idx & 3;
            size_t so = (size_t)(m0 + row) * 256 + kg + q * 8;
            uint32_t off = (uint32_t)row * 80 + q * 16;
            CPA(sb + AHI + off, Ah + so, 16u);
            CPA(sb + ALO + off, Al + so, 16u);
        }
    }
#pragma unroll
    for (int i = 0; i < 2; i++) {
        int idx = tid + i * 256;
        int row = idx >> 2, q = idx & 3;
        const __nv_bfloat16* src = wtL + (size_t)row * 512 + s * 32 + q * 8;
        uint32_t off = (uint32_t)row * 80 + q * 16;
        CPA(sb + BHI + off, src, 16u);
    }
}

__global__ void __launch_bounds__(256, 2)
gemm_mma_kernel(int layer, const float* __restrict__ bl_,
                const float* __restrict__ gamma, const float* __restrict__ beta) {
    extern __shared__ char sm[];
    __shared__ float sred[2][128][2];  // [wm][local col][{sum, sumsq}]
    __shared__ int is_last;
    uint32_t sb = smem_u32(sm);
    int tid = threadIdx.x;
    int lane = tid & 31, wid = tid >> 5;
    int wm = wid >> 2, wn = wid & 3;           // warp tile: 80(M) x 32(N)
    int m0 = blockIdx.x * MTILE, n0 = blockIdx.y * 128;
    const __nv_bfloat16* wtL = g_wt + (size_t)layer * 262144 + (size_t)n0 * 512;

    float C[5][4][4];
#pragma unroll
    for (int i = 0; i < 5; i++)
#pragma unroll
        for (int j = 0; j < 4; j++)
#pragma unroll
            for (int q = 0; q < 4; q++) C[i][j][q] = 0.0f;

    uint32_t a_row = (uint32_t)(wm * 80 + (lane & 15));
    uint32_t a_koff = (uint32_t)((lane >> 4) * 8);
    uint32_t b_row = (uint32_t)(wn * 32 + ((lane >> 4) & 1) * 8 + (lane & 7));
    uint32_t b_koff = (uint32_t)(((lane >> 3) & 1) * 8);

    load_stage(0, sb, m0, wtL);
    CPC();

    for (int s = 0; s < 16; s++) {
        if (s < 15) {
            load_stage(s + 1, sb + ((uint32_t)(s + 1) & 1u) * STAGE, m0, wtL);
            CPC();
            CPW(1);
        } else {
            CPW(0);
        }
        __syncthreads();
        uint32_t bufb = sb + ((uint32_t)s & 1u) * STAGE;
#pragma unroll
        for (int kl = 0; kl < 32; kl += 16) {
            uint32_t bh[2][4];
#pragma unroll
            for (int nf16 = 0; nf16 < 2; nf16++) {
                uint32_t ro = (b_row + nf16 * 16) * 80 + (b_koff + kl) * 2;
                LDSM4(bh[nf16], bufb + BHI + ro);
            }
#pragma unroll
            for (int mf = 0; mf < 5; mf++) {
                uint32_t ah[4], al[4];
                uint32_t ro = (a_row + mf * 16) * 80 + (a_koff + kl) * 2;
                LDSM4(ah, bufb + AHI + ro);
                LDSM4(al, bufb + ALO + ro);
#pragma unroll
                for (int nf = 0; nf < 4; nf++) {
                    uint32_t b0 = bh[nf >> 1][(nf & 1) * 2];
                    uint32_t b1 = bh[nf >> 1][(nf & 1) * 2 + 1];
                    MMA16816(C[mf][nf], ah, b0, b1);
                    MMA16816(C[mf][nf], al, b0, b1);
                }
            }
        }
        __syncthreads();
    }
    // ---- epilogue: bias + store + fused BN stats (rows always in-range) ----
    int mbase = m0 + wm * 80;
    int nbase = n0 + wn * 32;
    float ts[4][2], ts2[4][2];
#pragma unroll
    for (int nf = 0; nf < 4; nf++) {
        ts[nf][0] = ts[nf][1] = 0.f;
        ts2[nf][0] = ts2[nf][1] = 0.f;
    }
#pragma unroll
    for (int mf = 0; mf < 5; mf++) {
#pragma unroll
        for (int nf = 0; nf < 4; nf++) {
            int c = nbase + nf * 8 + (lane & 3) * 2;
            float bv0 = bl_[c], bv1 = bl_[c + 1];
            int r0 = mbase + mf * 16 + (lane >> 2);
            {
                float ox = C[mf][nf][0] + bv0, oy = C[mf][nf][1] + bv1;
                *(float2*)(g_h + (size_t)r0 * 256 + c) = make_float2(ox, oy);
                ts[nf][0] += ox; ts2[nf][0] += ox * ox;
                ts[nf][1] += oy; ts2[nf][1] += oy * oy;
            }
            {
                int r1 = r0 + 8;
                float ox = C[mf][nf][2] + bv0, oy = C[mf][nf][3] + bv1;
                *(float2*)(g_h + (size_t)r1 * 256 + c) = make_float2(ox, oy);
                ts[nf][0] += ox; ts2[nf][0] += ox * ox;
                ts[nf][1] += oy; ts2[nf][1] += oy * oy;
            }
        }
    }
#pragma unroll
    for (int nf = 0; nf < 4; nf++) {
#pragma unroll
        for (int i = 0; i < 2; i++) {
#pragma unroll
            for (int msk = 4; msk < 32; msk <<= 1) {
                ts[nf][i] += __shfl_xor_sync(0xFFFFFFFFu, ts[nf][i], msk);
                ts2[nf][i] += __shfl_xor_sync(0xFFFFFFFFu, ts2[nf][i], msk);
            }
        }
    }
    if (lane < 4) {
#pragma unroll
        for (int nf = 0; nf < 4; nf++) {
            int coll = wn * 32 + nf * 8 + lane * 2;
            sred[wm][coll][0] = ts[nf][0];
            sred[wm][coll][1] = ts2[nf][0];
            sred[wm][coll + 1][0] = ts[nf][1];
            sred[wm][coll + 1][1] = ts2[nf][1];
        }
    }
    __syncthreads();
    if (tid < 128) {
        float s = sred[0][tid][0] + sred[1][tid][0];
        float s2 = sred[0][tid][1] + sred[1][tid][1];
        int cg = blockIdx.x * 256 + n0 + tid;
        g_psum[cg] = s;
        g_psum2[cg] = s2;
    }
    // ---- fused bn_reduce: last block computes bn_a/bn_b ----
    __threadfence();
    __syncthreads();
    if (tid == 0) is_last = (atomicAdd(&g_ctr[layer], 1) == 2 * NB_STAT - 1);
    __syncthreads();
    if (is_last) {
        int d = tid;  // 0..255
        float s = 0, s2 = 0;
        for (int b = 0; b < NB_STAT; b++) {
            s += __ldcg(&g_psum[b * DIM + d]);
            s2 += __ldcg(&g_psum2[b * DIM + d]);
        }
        float mu = s / (float)NN;
        float var = s2 / (float)NN - mu * mu;
        float r = rsqrtf(var + EPS_BN);
        float a = gamma[d] * r;
        g_bn_a[d] = a;
        g_bn_b[d] = beta[d] - mu * a;
    }
}

// ---------------- fused tail: pool(bn+relu of h) + 3-layer MLP ---------------
__device__ __forceinline__ int lower_bound_batch(const int* __restrict__ batch, int g) {
    int lo = 0, hi = NN;
    while (lo < hi) {
        int mid = (lo + hi) >> 1;
        if (batch[mid] < g) lo = mid + 1; else hi = mid;
    }
    return lo;
}

__global__ void tail_kernel(const int* __restrict__ batch,
                            const float* __restrict__ fc1_w, const float* __restrict__ fc1_b,
                            const float* __restrict__ fc2_w, const float* __restrict__ fc2_b,
                            const float* __restrict__ fc3_w, const float* __restrict__ fc3_b,
                            float* __restrict__ out) {
    __shared__ float xr[256];
    __shared__ float y1[128];
    __shared__ float y2[64];
    int g = blockIdx.x;
    int n = threadIdx.x;  // 256 threads
    int r0 = lower_bound_batch(batch, g);
    int r1 = lower_bound_batch(batch, g + 1);
    float ba = g_bn_a[n], bb = g_bn_b[n];
    float s = 0;
#pragma unroll 4
    for (int r = r0; r < r1; r++) {
        float v = g_h[(size_t)r * DIM + n];
        s += fmaxf(v * ba + bb, 0.f);
    }
    int c = r1 - r0;
    xr[n] = s / (float)(c > 0 ? c : 1);
    __syncthreads();
    if (n < 128) {
        float t = fc1_b[n];
#pragma unroll 8
        for (int k = 0; k < 256; k++) t += xr[k] * fc1_w[k * 128 + n];
        y1[n] = fmaxf(t, 0.0f);
    }
    __syncthreads();
    if (n < 64) {
        float t = fc2_b[n];
#pragma unroll 8
        for (int k = 0; k < 128; k++) t += y1[k] * fc2_w[k * 64 + n];
        y2[n] = fmaxf(t, 0.0f);
    }
    __syncthreads();
    if (n < 10) {
        float t = fc3_b[n];
#pragma unroll 8
        for (int k = 0; k < 64; k++) t += y2[k] * fc3_w[k * 10 + n];
        out[g * 10 + n] = t;
    }
}

// ---------------- host launch ----------------
extern "C" void kernel_launch(void* const* d_in, const int* in_sizes, int n_in,
                              void* d_out, int out_size) {
    const float* x     = (const float*)d_in[0];
    const int*   ei    = (const int*)d_in[1];
    const int*   batch = (const int*)d_in[2];
    const float* Wl    = (const float*)d_in[3];
    const float* bl    = (const float*)d_in[4];
    const float* Wr    = (const float*)d_in[5];
    const float* gamma = (const float*)d_in[6];
    const float* beta  = (const float*)d_in[7];
    const float* fc1_w = (const float*)d_in[8];
    const float* fc1_b = (const float*)d_in[9];
    const float* fc2_w = (const float*)d_in[10];
    const float* fc2_b = (const float*)d_in[11];
    const float* fc3_w = (const float*)d_in[12];
    const float* fc3_b = (const float*)d_in[13];
    float* out = (float*)d_out;

    static bool attr_set = false;
    if (!attr_set) {
        cudaFuncSetAttribute(gemm_mma_kernel, cudaFuncAttributeMaxDynamicSharedMemorySize, GSM);
        cudaFuncSetAttribute(scan_kernel, cudaFuncAttributeMaxDynamicSharedMemorySize, NN * 4);
        attr_set = true;
    }

    // structure + conversions
    cvt_x_kernel<<<(NN * DIM / 8 + 255) / 256, 256>>>(x);   // also zeroes deg/fillpos/ctr
    deg_kernel<<<(NE + 255) / 256, 256>>>(ei);
    scan_kernel<<<1, 1024, NN * 4>>>();
    fill_kernel<<<(NE + 255) / 256, 256>>>(ei);
    reorder_kernel<<<(NN * 32 + 255) / 256, 256>>>();
    wtconv_kernel<<<dim3(16, 8, NLAYER), dim3(32, 32)>>>(Wl, Wr);

    for (int i = 0; i < NLAYER; i++) {
        if (i == 0)
            gather_kernel<false><<<(NN * 32 + 255) / 256, 256>>>(x);
        else
            gather_kernel<true><<<(NN * 32 + 255) / 256, 256>>>(nullptr);
        gemm_mma_kernel<<<dim3(NN / MTILE, 2), 256, GSM>>>(
            i, bl + (size_t)i * DIM, gamma + (size_t)i * DIM, beta + (size_t)i * DIM);
    }

    tail_kernel<<<NG, 256>>>(batch, fc1_w, fc1_b, fc2_w, fc2_b, fc3_w, fc3_b, out);
}